// round 6
// baseline (speedup 1.0000x reference)
#include <cuda_runtime.h>
#include <cuda_bf16.h>
#include <cstdint>

// ---------------- problem constants ----------------
constexpr int kL   = 512;
constexpr int kB   = 32;
constexpr int kEMB = 256;
constexpr int kH   = 128;   // per-direction hidden
constexpr int kG   = 512;   // 4*kH gate rows per direction
constexpr int kN   = 1024;  // both directions' gates
constexpr int kT   = 5;
constexpr int START = 3;
constexpr int STOP  = 4;

// ---------------- scratch (device globals; no allocs allowed) ----------------
__device__ __nv_bfloat16 g_xh[kL * kB * kEMB];   // x hi (bf16)
__device__ __nv_bfloat16 g_xl[kL * kB * kEMB];   // x lo (bf16 residual)
__device__ __nv_bfloat16 g_wh[kN * kEMB];        // [Wih_f;Wih_b] hi
__device__ __nv_bfloat16 g_wl[kN * kEMB];        // [Wih_f;Wih_b] lo
__device__ float g_gates[kL * kB * kN];          // (l,b,[fwd|bwd] gates)
__device__ float g_h[2 * kL * kB * kH];          // (dir,l,b,j)
__device__ float g_feats[kL * kB * kT];          // (l,b,tag)

// ---------------- small helpers ----------------
__device__ __forceinline__ float tanhapx(float x) {
    float y;
    asm("tanh.approx.f32 %0, %1;" : "=f"(y) : "f"(x));
    return y;
}
__device__ __forceinline__ float sigapx(float x) {
    return 0.5f * tanhapx(0.5f * x) + 0.5f;
}
__device__ __forceinline__ uint32_t smem_u32(const void* p) {
    uint32_t a;
    asm("{ .reg .u64 t; cvta.to.shared.u64 t, %1; cvt.u32.u64 %0, t; }" : "=r"(a) : "l"(p));
    return a;
}
__device__ __forceinline__ uint32_t swz128(uint32_t off) {
    return off ^ ((off >> 3) & 0x70);
}
__device__ __forceinline__ void cpasync16(uint32_t dst, const void* src) {
    asm volatile("cp.async.cg.shared.global [%0], [%1], 16;" :: "r"(dst), "l"(src));
}
__device__ __forceinline__ void ldsm4(uint32_t* r, uint32_t addr) {
    asm volatile("ldmatrix.sync.aligned.m8n8.x4.shared.b16 {%0,%1,%2,%3}, [%4];"
                 : "=r"(r[0]), "=r"(r[1]), "=r"(r[2]), "=r"(r[3]) : "r"(addr));
}
__device__ __forceinline__ void mma16816(float* d, const uint32_t* a, uint32_t b0, uint32_t b1) {
    asm volatile("mma.sync.aligned.m16n8k16.row.col.f32.bf16.bf16.f32 "
                 "{%0,%1,%2,%3}, {%4,%5,%6,%7}, {%8,%9}, {%0,%1,%2,%3};"
                 : "+f"(d[0]), "+f"(d[1]), "+f"(d[2]), "+f"(d[3])
                 : "r"(a[0]), "r"(a[1]), "r"(a[2]), "r"(a[3]), "r"(b0), "r"(b1));
}
// packed fp32x2 FMA (Blackwell dual fp32 path)
__device__ __forceinline__ void ffma2(unsigned long long& d, unsigned long long a,
                                      unsigned long long b) {
    asm("fma.rn.f32x2 %0, %1, %2, %3;" : "=l"(d) : "l"(a), "l"(b), "l"(d));
}
__device__ __forceinline__ float2 unpack2(unsigned long long v) {
    float lo, hi;
    asm("mov.b64 {%0, %1}, %2;" : "=f"(lo), "=f"(hi) : "l"(v));
    return make_float2(lo, hi);
}

// ---------------- K1: embedding gather + bf16 hi/lo split ----------------
__global__ void k_gather(const int* __restrict__ sent, const float* __restrict__ embed) {
    int lb = blockIdx.x;              // l*32 + b
    int l = lb >> 5, b = lb & 31;
    int tok = sent[b * kL + l];
    float4 v = ((const float4*)(embed + (size_t)tok * kEMB))[threadIdx.x];
    float xs[4] = {v.x, v.y, v.z, v.w};
    ushort4 hp, lp;
    unsigned short* hpp = (unsigned short*)&hp;
    unsigned short* lpp = (unsigned short*)&lp;
#pragma unroll
    for (int i = 0; i < 4; i++) {
        __nv_bfloat16 h = __float2bfloat16_rn(xs[i]);
        __nv_bfloat16 lo = __float2bfloat16_rn(xs[i] - __bfloat162float(h));
        hpp[i] = *(unsigned short*)&h;
        lpp[i] = *(unsigned short*)&lo;
    }
    size_t o = (size_t)lb * kEMB + threadIdx.x * 4;
    *(ushort4*)(g_xh + o) = hp;
    *(ushort4*)(g_xl + o) = lp;
}

// ---------------- K1b: weight bf16 hi/lo split ----------------
__global__ void k_wconv(const float* __restrict__ Wf, const float* __restrict__ Wb) {
    int row = blockIdx.x;             // 0..1023
    int k = threadIdx.x;              // 0..255
    float v = (row < kG) ? Wf[(size_t)row * kEMB + k] : Wb[(size_t)(row - kG) * kEMB + k];
    __nv_bfloat16 h = __float2bfloat16_rn(v);
    __nv_bfloat16 lo = __float2bfloat16_rn(v - __bfloat162float(h));
    g_wh[(size_t)row * kEMB + k] = h;
    g_wl[(size_t)row * kEMB + k] = lo;
}

// ---------------- K2: mma.sync bf16 GEMM  g_gates = x @ W^T + bias ----------------
constexpr int GKC = 64;                 // K per chunk (bf16)
constexpr int NCHUNK = 12;              // 768 / 64
constexpr int GBUF = 32768;             // A(16KB)+B(16KB) per buffer
constexpr int GEMM_SMEM = 2 * GBUF;     // 64 KB

__device__ __forceinline__ void ld_chunk(uint32_t sbase, int ck, int buf, int m0, int n0) {
    const int tid = threadIdx.x;
    const int seg = ck >> 2;
    const int koff = (ck & 3) * GKC;
    const __nv_bfloat16* Ag = (seg < 2) ? g_xh : g_xl;
    const __nv_bfloat16* Bg = (seg == 1) ? g_wl : g_wh;
    const uint32_t abase = sbase + buf * GBUF;
    const uint32_t bbase = abase + 16384;
#pragma unroll
    for (int i = 0; i < 4; i++) {
        int idx = i * 256 + tid;        // 0..1023 : 128 rows x 8 16B-chunks
        int r = idx >> 3;
        int c8 = idx & 7;               // 16B chunk within 128B row
        uint32_t so = swz128((uint32_t)(r * 128 + c8 * 16));
        cpasync16(abase + so, Ag + (size_t)(m0 + r) * kEMB + koff + c8 * 8);
        cpasync16(bbase + so, Bg + (size_t)(n0 + r) * kEMB + koff + c8 * 8);
    }
}

__global__ __launch_bounds__(256, 2) void k_gemm_mma(const float* __restrict__ biasf,
                                                     const float* __restrict__ biasb) {
    extern __shared__ __align__(1024) char smem[];
    const uint32_t sbase = smem_u32(smem);
    const int tid = threadIdx.x;
    const int wid = tid >> 5;
    const int lane = tid & 31;
    const int m0 = blockIdx.y * 128;
    const int n0 = blockIdx.x * 128;
    const int wm = (wid & 1) * 64;      // warp M offset in tile
    const int wn = (wid >> 1) * 32;     // warp N offset in tile

    float acc[4][4][4];
#pragma unroll
    for (int a = 0; a < 4; a++)
#pragma unroll
        for (int b = 0; b < 4; b++)
#pragma unroll
            for (int c = 0; c < 4; c++) acc[a][b][c] = 0.0f;

    ld_chunk(sbase, 0, 0, m0, n0);
    asm volatile("cp.async.commit_group;");

    const int rbase = (lane & 7) + ((lane >> 3) & 1) * 8;
    const int cext = (lane >> 4) * 16;

    for (int ck = 0; ck < NCHUNK; ck++) {
        if (ck + 1 < NCHUNK) ld_chunk(sbase, ck + 1, (ck + 1) & 1, m0, n0);
        asm volatile("cp.async.commit_group;");
        asm volatile("cp.async.wait_group 1;");
        __syncthreads();

        const uint32_t abuf = sbase + (ck & 1) * GBUF;
        const uint32_t bbuf = abuf + 16384;
#pragma unroll
        for (int k16 = 0; k16 < 4; k16++) {
            const int cb = k16 * 32 + cext;
            uint32_t a[4][4];
#pragma unroll
            for (int mi = 0; mi < 4; mi++)
                ldsm4(a[mi], abuf + swz128((uint32_t)((wm + mi * 16 + rbase) * 128 + cb)));
            uint32_t bfr[2][4];
#pragma unroll
            for (int p = 0; p < 2; p++)
                ldsm4(bfr[p], bbuf + swz128((uint32_t)((wn + p * 16 + rbase) * 128 + cb)));
#pragma unroll
            for (int mi = 0; mi < 4; mi++)
#pragma unroll
                for (int nj = 0; nj < 4; nj++)
                    mma16816(acc[mi][nj], a[mi], bfr[nj >> 1][nj & 1], bfr[nj >> 1][(nj & 1) + 2]);
        }
        __syncthreads();
    }

    // epilogue + bias
#pragma unroll
    for (int mi = 0; mi < 4; mi++) {
        int row = m0 + wm + mi * 16 + (lane >> 2);
#pragma unroll
        for (int nj = 0; nj < 4; nj++) {
            int col = n0 + wn + nj * 8 + (lane & 3) * 2;
            float bx = (col < kG) ? biasf[col] : biasb[col - kG];
            float by = (col + 1 < kG) ? biasf[col + 1] : biasb[col + 1 - kG];
            float2 v0 = make_float2(acc[mi][nj][0] + bx, acc[mi][nj][1] + by);
            float2 v1 = make_float2(acc[mi][nj][2] + bx, acc[mi][nj][3] + by);
            *(float2*)(g_gates + (size_t)row * kN + col) = v0;
            *(float2*)(g_gates + (size_t)(row + 8) * kN + col) = v1;
        }
    }
}

// ---------------- K3: LSTM recurrence (quad-shuffle fused epilogue) ----------------
// 64 blocks (chain = dir*32+b), 512 threads. Thread t: unit j=t>>2, gate g=t&3,
// owns gate row r = g*128 + j. Whh row split: cols 0..79 regs, 80..127 smem.
// One __syncthreads per step (double-buffered h_s); gates exchanged via quad shfl.
constexpr int WREG4 = 20;                    // float4 groups in registers (80 cols)
constexpr int WSM4  = 12;                    // float4 groups in smem (48 cols)
constexpr int SW_FLOATS = WSM4 * 512 * 4;    // 24576 floats = 96 KB

__global__ __launch_bounds__(512, 1) void k_lstm(const float* __restrict__ Whh_f,
                                                 const float* __restrict__ Whh_b,
                                                 const float* __restrict__ h0,
                                                 const float* __restrict__ c0) {
    extern __shared__ float sm[];
    float* sw  = sm;                    // spread weights
    float* h_s = sm + SW_FLOATS;        // 2 x 128 floats (double buffer)

    const int t   = threadIdx.x;
    const int j   = t >> 2;             // hidden unit 0..127
    const int g   = t & 3;              // gate 0..3 (i,f,g,o)
    const int r   = g * kH + j;         // gate row in [0,512)
    const int blk = blockIdx.x;
    const int dir = blk >> 5;
    const int b   = blk & 31;
    const float* Whh = dir ? Whh_b : Whh_f;

    ulonglong2 wp[WREG4];
#pragma unroll
    for (int i = 0; i < WREG4; i++)
        wp[i] = *(const ulonglong2*)(Whh + (size_t)r * kH + i * 4);
#pragma unroll
    for (int i = 0; i < WSM4; i++) {
        float4 v = *(const float4*)(Whh + (size_t)r * kH + WREG4 * 4 + i * 4);
        *(float4*)(sw + ((size_t)i * 512 + t) * 4) = v;
    }

    float c = c0[(dir * kB + b) * kH + j];          // per-unit cell (replicated x4)
    if (g == 0) h_s[j] = h0[(dir * kB + b) * kH + j];
    __syncthreads();

    int l = dir ? (kL - 1) : 0;
    const int step = dir ? -1 : 1;
    const int gofs = dir ? kG : 0;
    int cur = 0;

    float pre = g_gates[((size_t)l * kB + b) * kN + gofs + r];

    for (int s = 0; s < kL; s++) {
        int ln = l + step;
        int lnc = min(max(ln, 0), kL - 1);
        float pre_next = g_gates[((size_t)lnc * kB + b) * kN + gofs + r];

        // ---- dot: acc = pre + W[r,:] . h ----
        unsigned long long acc01, acc23;
        asm("mov.b64 %0, {%1, %2};" : "=l"(acc01) : "f"(pre), "f"(0.0f));
        acc23 = 0ULL;
        const ulonglong2* h2 = (const ulonglong2*)(h_s + cur * 128);
#pragma unroll
        for (int i = 0; i < WREG4; i++) {
            ulonglong2 hv = h2[i];
            ffma2(acc01, wp[i].x, hv.x);
            ffma2(acc23, wp[i].y, hv.y);
        }
#pragma unroll
        for (int i = 0; i < WSM4; i++) {
            ulonglong2 hv = h2[WREG4 + i];
            ulonglong2 wv = *(const ulonglong2*)(sw + ((size_t)i * 512 + t) * 4);
            ffma2(acc01, wv.x, hv.x);
            ffma2(acc23, wv.y, hv.y);
        }
        float2 p01 = unpack2(acc01);
        float2 p23 = unpack2(acc23);
        float v = (p01.x + p01.y) + (p23.x + p23.y);

        // ---- quad exchange: gather all 4 gates of unit j ----
        float vx = __shfl_xor_sync(0xffffffffu, v, 1);
        float vy = __shfl_xor_sync(0xffffffffu, v, 2);
        float vz = __shfl_xor_sync(0xffffffffu, vx, 2);
        // value of gate k sits at xor-distance d=k^g: {0:v, 1:vx, 2:vy, 3:vz}
        float gv[4];
#pragma unroll
        for (int k = 0; k < 4; k++) {
            int d = k ^ g;
            gv[k] = (d & 1) ? ((d & 2) ? vz : vx) : ((d & 2) ? vy : v);
        }
        // ---- epilogue (replicated across the quad, deterministic) ----
        c = sigapx(gv[1]) * c + sigapx(gv[0]) * tanhapx(gv[2]);
        float h = sigapx(gv[3]) * tanhapx(c);
        int nxt = cur ^ 1;
        if (g == 0) {
            h_s[nxt * 128 + j] = h;
            g_h[(((size_t)dir * kL + l) * kB + b) * kH + j] = h;
        }
        __syncthreads();

        cur = nxt;
        pre = pre_next;
        l = ln;
    }
}

// ---------------- K4: feats = concat(hf,hb) @ W_tag^T + b_tag ----------------
__global__ void k_feats(const float* __restrict__ Wt, const float* __restrict__ bt) {
    int lb = blockIdx.x * 8 + (threadIdx.x >> 5);
    int lane = threadIdx.x & 31;
    const float4* hbase = (const float4*)g_h;
    float4 a = hbase[(size_t)lb * 32 + lane];
    float4 cc = hbase[(size_t)kL * kB * 32 + (size_t)lb * 32 + lane];
#pragma unroll
    for (int tag = 0; tag < kT; tag++) {
        float4 w0 = *(const float4*)(Wt + tag * 2 * kH + lane * 4);
        float4 w1 = *(const float4*)(Wt + tag * 2 * kH + kH + lane * 4);
        float p = a.x * w0.x + a.y * w0.y + a.z * w0.z + a.w * w0.w
                + cc.x * w1.x + cc.y * w1.y + cc.z * w1.z + cc.w * w1.w;
        p += __shfl_xor_sync(0xffffffffu, p, 16);
        p += __shfl_xor_sync(0xffffffffu, p, 8);
        p += __shfl_xor_sync(0xffffffffu, p, 4);
        p += __shfl_xor_sync(0xffffffffu, p, 2);
        p += __shfl_xor_sync(0xffffffffu, p, 1);
        if (lane == 0) g_feats[(size_t)lb * kT + tag] = p + bt[tag];
    }
}

// ---------------- K5: CRF forward scan + gold score ----------------
__global__ __launch_bounds__(512) void k_crf(const int* __restrict__ tags,
                                             const int* __restrict__ mask,
                                             const float* __restrict__ tr,
                                             float* __restrict__ out) {
    __shared__ float fwd_s[kB];
    __shared__ float gold_s[kB];
    const int tid = threadIdx.x;
    const int w = tid >> 5, lane = tid & 31;

    if (w < 8) {
        const int bi = lane >> 3;
        const int i  = lane & 7;
        const int b  = w * 4 + bi;
        const int ie = (i < kT) ? i : (kT - 1);
        const int base = lane & 24;

        float tr0 = tr[ie * kT + 0], tr1 = tr[ie * kT + 1], tr2 = tr[ie * kT + 2];
        float tr3 = tr[ie * kT + 3], tr4 = tr[ie * kT + 4];
        float alpha = (i == START) ? 0.0f : -10000.0f;
        const int mb = mask[b];
        float amask = 0.0f;

        for (int l = 1; l <= kL - 2; l++) {
            float f = g_feats[((size_t)l * kB + b) * kT + ie];
            float a0 = __shfl_sync(0xffffffffu, alpha, base + 0);
            float a1 = __shfl_sync(0xffffffffu, alpha, base + 1);
            float a2 = __shfl_sync(0xffffffffu, alpha, base + 2);
            float a3 = __shfl_sync(0xffffffffu, alpha, base + 3);
            float a4 = __shfl_sync(0xffffffffu, alpha, base + 4);
            float v0 = a0 + tr0, v1 = a1 + tr1, v2 = a2 + tr2;
            float v3 = a3 + tr3, v4 = a4 + tr4;
            float m = fmaxf(fmaxf(fmaxf(v0, v1), fmaxf(v2, v3)), v4);
            float ssum = __expf(v0 - m) + __expf(v1 - m) + __expf(v2 - m)
                       + __expf(v3 - m) + __expf(v4 - m);
            alpha = f + m + __logf(ssum);
            if (l == mb) amask = alpha;
        }
        float t0 = __shfl_sync(0xffffffffu, amask, base + 0) + tr[STOP * kT + 0];
        float t1 = __shfl_sync(0xffffffffu, amask, base + 1) + tr[STOP * kT + 1];
        float t2 = __shfl_sync(0xffffffffu, amask, base + 2) + tr[STOP * kT + 2];
        float t3 = __shfl_sync(0xffffffffu, amask, base + 3) + tr[STOP * kT + 3];
        float t4 = __shfl_sync(0xffffffffu, amask, base + 4) + tr[STOP * kT + 4];
        float m = fmaxf(fmaxf(fmaxf(t0, t1), fmaxf(t2, t3)), t4);
        float ssum = __expf(t0 - m) + __expf(t1 - m) + __expf(t2 - m)
                   + __expf(t3 - m) + __expf(t4 - m);
        if (i == 0) fwd_s[b] = m + __logf(ssum);
    } else if (w < 16) {
        const int b = (w - 8) * 4 + (lane >> 3);
        const int lp = lane & 7;
        const int mb = mask[b];
        float s = 0.0f;
        for (int p = lp; p < mb; p += 8) {
            int tp = tags[b * kL + p];
            int tn = tags[b * kL + p + 1];
            s += tr[tn * kT + tp] + g_feats[((size_t)(p + 1) * kB + b) * kT + tn];
        }
        s += __shfl_xor_sync(0xffffffffu, s, 4);
        s += __shfl_xor_sync(0xffffffffu, s, 2);
        s += __shfl_xor_sync(0xffffffffu, s, 1);
        if (lp == 0) gold_s[b] = s + tr[STOP * kT + tags[b * kL + mb]];
    }
    __syncthreads();
    if (tid == 0) {
        float fs = 0.0f, gs = 0.0f;
        for (int bb = 0; bb < kB; bb++) { fs += fwd_s[bb]; gs += gold_s[bb]; }
        out[0] = (fs - gs) * (1.0f / kB);
    }
}

// ---------------- launch ----------------
extern "C" void kernel_launch(void* const* d_in, const int* in_sizes, int n_in,
                              void* d_out, int out_size) {
    const int*   sentence = (const int*)d_in[0];
    const int*   tags     = (const int*)d_in[1];
    const int*   mask     = (const int*)d_in[2];
    const float* embed    = (const float*)d_in[3];
    const float* Wih_f    = (const float*)d_in[4];
    const float* Whh_f    = (const float*)d_in[5];
    const float* b_f      = (const float*)d_in[6];
    const float* Wih_b    = (const float*)d_in[7];
    const float* Whh_b    = (const float*)d_in[8];
    const float* b_b      = (const float*)d_in[9];
    const float* W_tag    = (const float*)d_in[10];
    const float* b_tag    = (const float*)d_in[11];
    const float* trans    = (const float*)d_in[12];
    const float* h0       = (const float*)d_in[13];
    const float* c0       = (const float*)d_in[14];
    (void)in_sizes; (void)n_in; (void)out_size;

    const int lstm_smem = (SW_FLOATS + 256) * (int)sizeof(float);
    cudaFuncSetAttribute(k_lstm, cudaFuncAttributeMaxDynamicSharedMemorySize, lstm_smem);
    cudaFuncSetAttribute(k_gemm_mma, cudaFuncAttributeMaxDynamicSharedMemorySize, GEMM_SMEM);

    k_gather<<<kL * kB, 64>>>(sentence, embed);
    k_wconv<<<kN, kEMB>>>(Wih_f, Wih_b);

    dim3 gg(kN / 128, (kL * kB) / 128);   // (8, 128)
    k_gemm_mma<<<gg, 256, GEMM_SMEM>>>(b_f, b_b);

    k_lstm<<<64, 512, lstm_smem>>>(Whh_f, Whh_b, h0, c0);

    k_feats<<<(kL * kB) / 8, 256>>>(W_tag, b_tag);

    k_crf<<<1, 512>>>(tags, mask, trans, (float*)d_out);
}

// round 8
// speedup vs baseline: 1.2911x; 1.2911x over previous
#include <cuda_runtime.h>
#include <cuda_bf16.h>
#include <cstdint>

// ---------------- problem constants ----------------
constexpr int kL   = 512;
constexpr int kB   = 32;
constexpr int kEMB = 256;
constexpr int kH   = 128;   // per-direction hidden
constexpr int kG   = 512;   // 4*kH gate rows per direction
constexpr int kN   = 1024;  // both directions' gates
constexpr int kT   = 5;
constexpr int START = 3;
constexpr int STOP  = 4;

// ---------------- scratch (device globals; no allocs allowed) ----------------
__device__ __nv_bfloat16 g_xh[kL * kB * kEMB];   // x hi (bf16)
__device__ __nv_bfloat16 g_xl[kL * kB * kEMB];   // x lo (bf16 residual)
__device__ __nv_bfloat16 g_wh[kN * kEMB];        // [Wih_f;Wih_b] hi
__device__ __nv_bfloat16 g_wl[kN * kEMB];        // [Wih_f;Wih_b] lo
__device__ float g_gates[kL * kB * kN];          // (l,b,[fwd|bwd] gates)
__device__ float g_h[2 * kL * kB * kH];          // (dir,l,b,j)
__device__ float g_feats[kL * kB * kT];          // (l,b,tag)

// ---------------- small helpers ----------------
__device__ __forceinline__ float tanhapx(float x) {
    float y;
    asm("tanh.approx.f32 %0, %1;" : "=f"(y) : "f"(x));
    return y;
}
__device__ __forceinline__ float sigapx(float x) {
    return 0.5f * tanhapx(0.5f * x) + 0.5f;
}
__device__ __forceinline__ uint32_t smem_u32(const void* p) {
    uint32_t a;
    asm("{ .reg .u64 t; cvta.to.shared.u64 t, %1; cvt.u32.u64 %0, t; }" : "=r"(a) : "l"(p));
    return a;
}
__device__ __forceinline__ uint32_t swz128(uint32_t off) {
    return off ^ ((off >> 3) & 0x70);
}
__device__ __forceinline__ void cpasync16(uint32_t dst, const void* src) {
    asm volatile("cp.async.cg.shared.global [%0], [%1], 16;" :: "r"(dst), "l"(src));
}
__device__ __forceinline__ void ldsm4(uint32_t* r, uint32_t addr) {
    asm volatile("ldmatrix.sync.aligned.m8n8.x4.shared.b16 {%0,%1,%2,%3}, [%4];"
                 : "=r"(r[0]), "=r"(r[1]), "=r"(r[2]), "=r"(r[3]) : "r"(addr));
}
__device__ __forceinline__ void mma16816(float* d, const uint32_t* a, uint32_t b0, uint32_t b1) {
    asm volatile("mma.sync.aligned.m16n8k16.row.col.f32.bf16.bf16.f32 "
                 "{%0,%1,%2,%3}, {%4,%5,%6,%7}, {%8,%9}, {%0,%1,%2,%3};"
                 : "+f"(d[0]), "+f"(d[1]), "+f"(d[2]), "+f"(d[3])
                 : "r"(a[0]), "r"(a[1]), "r"(a[2]), "r"(a[3]), "r"(b0), "r"(b1));
}
// packed fp32x2 FMA
__device__ __forceinline__ void ffma2(unsigned long long& d, unsigned long long a,
                                      unsigned long long b) {
    asm("fma.rn.f32x2 %0, %1, %2, %3;" : "=l"(d) : "l"(a), "l"(b), "l"(d));
}
__device__ __forceinline__ float2 unpack2(unsigned long long v) {
    float lo, hi;
    asm("mov.b64 {%0, %1}, %2;" : "=f"(lo), "=f"(hi) : "l"(v));
    return make_float2(lo, hi);
}
// bf16x2 pack: hi goes to upper half, lo to lower half
__device__ __forceinline__ uint32_t bfpack(float hi, float lo) {
    uint32_t d;
    asm("cvt.rn.bf16x2.f32 %0, %1, %2;" : "=r"(d) : "f"(hi), "f"(lo));
    return d;
}
__device__ __forceinline__ uint32_t hfma2bf(uint32_t a, uint32_t b, uint32_t c) {
    uint32_t d;
    asm("fma.rn.bf16x2 %0, %1, %2, %3;" : "=r"(d) : "r"(a), "r"(b), "r"(c));
    return d;
}
// unpack bf16x2 -> two fp32 via bit shifts (ALU pipe)
__device__ __forceinline__ float bflo(uint32_t v) { return __uint_as_float(v << 16); }
__device__ __forceinline__ float bfhi(uint32_t v) { return __uint_as_float(v & 0xffff0000u); }

// ---------------- K1: embedding gather + bf16 hi/lo split ----------------
__global__ void k_gather(const int* __restrict__ sent, const float* __restrict__ embed) {
    int lb = blockIdx.x;              // l*32 + b
    int l = lb >> 5, b = lb & 31;
    int tok = sent[b * kL + l];
    float4 v = ((const float4*)(embed + (size_t)tok * kEMB))[threadIdx.x];
    float xs[4] = {v.x, v.y, v.z, v.w};
    ushort4 hp, lp;
    unsigned short* hpp = (unsigned short*)&hp;
    unsigned short* lpp = (unsigned short*)&lp;
#pragma unroll
    for (int i = 0; i < 4; i++) {
        __nv_bfloat16 h = __float2bfloat16_rn(xs[i]);
        __nv_bfloat16 lo = __float2bfloat16_rn(xs[i] - __bfloat162float(h));
        hpp[i] = *(unsigned short*)&h;
        lpp[i] = *(unsigned short*)&lo;
    }
    size_t o = (size_t)lb * kEMB + threadIdx.x * 4;
    *(ushort4*)(g_xh + o) = hp;
    *(ushort4*)(g_xl + o) = lp;
}

// ---------------- K1b: weight bf16 hi/lo split ----------------
__global__ void k_wconv(const float* __restrict__ Wf, const float* __restrict__ Wb) {
    int row = blockIdx.x;             // 0..1023
    int k = threadIdx.x;              // 0..255
    float v = (row < kG) ? Wf[(size_t)row * kEMB + k] : Wb[(size_t)(row - kG) * kEMB + k];
    __nv_bfloat16 h = __float2bfloat16_rn(v);
    __nv_bfloat16 lo = __float2bfloat16_rn(v - __bfloat162float(h));
    g_wh[(size_t)row * kEMB + k] = h;
    g_wl[(size_t)row * kEMB + k] = lo;
}

// ---------------- K2: mma.sync bf16 GEMM  g_gates = x @ W^T + bias ----------------
constexpr int GKC = 64;                 // K per chunk (bf16)
constexpr int NCHUNK = 12;              // 768 / 64
constexpr int GBUF = 32768;             // A(16KB)+B(16KB) per buffer
constexpr int GEMM_SMEM = 2 * GBUF;     // 64 KB

__device__ __forceinline__ void ld_chunk(uint32_t sbase, int ck, int buf, int m0, int n0) {
    const int tid = threadIdx.x;
    const int seg = ck >> 2;
    const int koff = (ck & 3) * GKC;
    const __nv_bfloat16* Ag = (seg < 2) ? g_xh : g_xl;
    const __nv_bfloat16* Bg = (seg == 1) ? g_wl : g_wh;
    const uint32_t abase = sbase + buf * GBUF;
    const uint32_t bbase = abase + 16384;
#pragma unroll
    for (int i = 0; i < 4; i++) {
        int idx = i * 256 + tid;        // 0..1023 : 128 rows x 8 16B-chunks
        int r = idx >> 3;
        int c8 = idx & 7;               // 16B chunk within 128B row
        uint32_t so = swz128((uint32_t)(r * 128 + c8 * 16));
        cpasync16(abase + so, Ag + (size_t)(m0 + r) * kEMB + koff + c8 * 8);
        cpasync16(bbase + so, Bg + (size_t)(n0 + r) * kEMB + koff + c8 * 8);
    }
}

__global__ __launch_bounds__(256, 2) void k_gemm_mma(const float* __restrict__ biasf,
                                                     const float* __restrict__ biasb) {
    extern __shared__ __align__(1024) char smem[];
    const uint32_t sbase = smem_u32(smem);
    const int tid = threadIdx.x;
    const int wid = tid >> 5;
    const int lane = tid & 31;
    const int m0 = blockIdx.y * 128;
    const int n0 = blockIdx.x * 128;
    const int wm = (wid & 1) * 64;      // warp M offset in tile
    const int wn = (wid >> 1) * 32;     // warp N offset in tile

    float acc[4][4][4];
#pragma unroll
    for (int a = 0; a < 4; a++)
#pragma unroll
        for (int b = 0; b < 4; b++)
#pragma unroll
            for (int c = 0; c < 4; c++) acc[a][b][c] = 0.0f;

    ld_chunk(sbase, 0, 0, m0, n0);
    asm volatile("cp.async.commit_group;");

    const int rbase = (lane & 7) + ((lane >> 3) & 1) * 8;
    const int cext = (lane >> 4) * 16;

    for (int ck = 0; ck < NCHUNK; ck++) {
        if (ck + 1 < NCHUNK) ld_chunk(sbase, ck + 1, (ck + 1) & 1, m0, n0);
        asm volatile("cp.async.commit_group;");
        asm volatile("cp.async.wait_group 1;");
        __syncthreads();

        const uint32_t abuf = sbase + (ck & 1) * GBUF;
        const uint32_t bbuf = abuf + 16384;
#pragma unroll
        for (int k16 = 0; k16 < 4; k16++) {
            const int cb = k16 * 32 + cext;
            uint32_t a[4][4];
#pragma unroll
            for (int mi = 0; mi < 4; mi++)
                ldsm4(a[mi], abuf + swz128((uint32_t)((wm + mi * 16 + rbase) * 128 + cb)));
            uint32_t bfr[2][4];
#pragma unroll
            for (int p = 0; p < 2; p++)
                ldsm4(bfr[p], bbuf + swz128((uint32_t)((wn + p * 16 + rbase) * 128 + cb)));
#pragma unroll
            for (int mi = 0; mi < 4; mi++)
#pragma unroll
                for (int nj = 0; nj < 4; nj++)
                    mma16816(acc[mi][nj], a[mi], bfr[nj >> 1][nj & 1], bfr[nj >> 1][(nj & 1) + 2]);
        }
        __syncthreads();
    }

    // epilogue + bias
#pragma unroll
    for (int mi = 0; mi < 4; mi++) {
        int row = m0 + wm + mi * 16 + (lane >> 2);
#pragma unroll
        for (int nj = 0; nj < 4; nj++) {
            int col = n0 + wn + nj * 8 + (lane & 3) * 2;
            float bx = (col < kG) ? biasf[col] : biasb[col - kG];
            float by = (col + 1 < kG) ? biasf[col + 1] : biasb[col + 1 - kG];
            float2 v0 = make_float2(acc[mi][nj][0] + bx, acc[mi][nj][1] + by);
            float2 v1 = make_float2(acc[mi][nj][2] + bx, acc[mi][nj][3] + by);
            *(float2*)(g_gates + (size_t)row * kN + col) = v0;
            *(float2*)(g_gates + (size_t)(row + 8) * kN + col) = v1;
        }
    }
}

// ---------------- K3: LSTM recurrence ----------------
// 64 blocks (chain = dir*32+b), 512 threads, thread t owns gate row t.
// Whh row split: cols 0..79 fp32 in regs (20 x f32x2-pair groups),
//                cols 80..127 bf16x2 in smem (6 x uint4 per row, spread layout).
// h kept both as fp32 (cols 0..79 consumers) and bf16x2 (cols 80..127 consumers).
constexpr int WREG4 = 20;                       // fp32 float4-groups in regs (80 cols)
constexpr int SWB_U4 = 6;                       // uint4 groups (8 bf16 cols each) in smem
constexpr int SWB_BYTES = SWB_U4 * 512 * 16;    // 48 KB
constexpr int LSTM_SMEM = SWB_BYTES + (128 + 512) * 4 + 128;

__global__ __launch_bounds__(512, 1) void k_lstm(const float* __restrict__ Whh_f,
                                                 const float* __restrict__ Whh_b,
                                                 const float* __restrict__ h0,
                                                 const float* __restrict__ c0) {
    extern __shared__ uint4 smu[];
    uint4* swb = smu;                                // [6*512] bf16x2 weights
    float* h_s = (float*)(smu + SWB_U4 * 512);       // 128 fp32
    float* g_s = h_s + 128;                          // 512 fp32
    uint32_t* h_bf = (uint32_t*)(g_s + 512);         // 24 u32 (cols 80..127 pairs)

    const int t   = threadIdx.x;
    const int blk = blockIdx.x;
    const int dir = blk >> 5;
    const int b   = blk & 31;
    const float* Whh = dir ? Whh_b : Whh_f;

    // register weights: cols 0..79 fp32
    ulonglong2 wp[WREG4];
#pragma unroll
    for (int i = 0; i < WREG4; i++)
        wp[i] = *(const ulonglong2*)(Whh + (size_t)t * kH + i * 4);
    // smem weights: cols 80..127 packed bf16x2, spread layout [grp][t]
#pragma unroll
    for (int gp = 0; gp < SWB_U4; gp++) {
        float4 a = *(const float4*)(Whh + (size_t)t * kH + 80 + gp * 8);
        float4 c4 = *(const float4*)(Whh + (size_t)t * kH + 80 + gp * 8 + 4);
        uint4 pk;
        pk.x = bfpack(a.y, a.x);
        pk.y = bfpack(a.w, a.z);
        pk.z = bfpack(c4.y, c4.x);
        pk.w = bfpack(c4.w, c4.z);
        swb[gp * 512 + t] = pk;
    }

    float c = 0.0f;
    {
        float hini = 0.0f;
        if (t < kH) {
            c = c0[(dir * kB + b) * kH + t];
            hini = h0[(dir * kB + b) * kH + t];
            h_s[t] = hini;
            float hn = __shfl_down_sync(0xffffffffu, hini, 1);
            if (t >= 80 && !(t & 1)) h_bf[(t - 80) >> 1] = bfpack(hn, hini);
        }
    }
    __syncthreads();

    int l = dir ? (kL - 1) : 0;
    const int step = dir ? -1 : 1;
    const int gofs = dir ? kG : 0;

    float pre = g_gates[((size_t)l * kB + b) * kN + gofs + t];

    for (int s = 0; s < kL; s++) {
        int ln = l + step;
        int lnc = min(max(ln, 0), kL - 1);
        float pre_next = g_gates[((size_t)lnc * kB + b) * kN + gofs + t];

        // ---- fp32 part: cols 0..79 ----
        unsigned long long acc01, acc23;
        asm("mov.b64 %0, {%1, %2};" : "=l"(acc01) : "f"(pre), "f"(0.0f));
        acc23 = 0ULL;
        const ulonglong2* h2 = (const ulonglong2*)h_s;
#pragma unroll
        for (int i = 0; i < WREG4; i++) {
            ulonglong2 hv = h2[i];
            ffma2(acc01, wp[i].x, hv.x);
            ffma2(acc23, wp[i].y, hv.y);
        }
        // ---- bf16 part: cols 80..127 (two independent bf16x2 accumulators) ----
        uint32_t ba = 0u, bb2 = 0u;
        const uint4* hb4 = (const uint4*)h_bf;
#pragma unroll
        for (int gp = 0; gp < SWB_U4; gp++) {
            uint4 wv = swb[gp * 512 + t];
            uint4 hv = hb4[gp];
            if (gp < 3) {
                ba = hfma2bf(wv.x, hv.x, ba);
                ba = hfma2bf(wv.y, hv.y, ba);
                ba = hfma2bf(wv.z, hv.z, ba);
                ba = hfma2bf(wv.w, hv.w, ba);
            } else {
                bb2 = hfma2bf(wv.x, hv.x, bb2);
                bb2 = hfma2bf(wv.y, hv.y, bb2);
                bb2 = hfma2bf(wv.z, hv.z, bb2);
                bb2 = hfma2bf(wv.w, hv.w, bb2);
            }
        }
        float2 p01 = unpack2(acc01);
        float2 p23 = unpack2(acc23);
        float v = ((p01.x + p01.y) + (p23.x + p23.y))
                + ((bflo(ba) + bfhi(ba)) + (bflo(bb2) + bfhi(bb2)));
        g_s[t] = v;
        __syncthreads();

        if (t < kH) {
            float gi = g_s[t];
            float gf = g_s[kH + t];
            float gg = g_s[2 * kH + t];
            float go = g_s[3 * kH + t];
            c = sigapx(gf) * c + sigapx(gi) * tanhapx(gg);
            float h = sigapx(go) * tanhapx(c);
            float hn = __shfl_down_sync(0xffffffffu, h, 1);
            h_s[t] = h;
            if (t >= 80 && !(t & 1)) h_bf[(t - 80) >> 1] = bfpack(hn, h);
            g_h[(((size_t)dir * kL + l) * kB + b) * kH + t] = h;
        }
        __syncthreads();

        pre = pre_next;
        l = ln;
    }
}

// ---------------- K4: feats = concat(hf,hb) @ W_tag^T + b_tag ----------------
__global__ void k_feats(const float* __restrict__ Wt, const float* __restrict__ bt) {
    int lb = blockIdx.x * 8 + (threadIdx.x >> 5);
    int lane = threadIdx.x & 31;
    const float4* hbase = (const float4*)g_h;
    float4 a = hbase[(size_t)lb * 32 + lane];
    float4 cc = hbase[(size_t)kL * kB * 32 + (size_t)lb * 32 + lane];
#pragma unroll
    for (int tag = 0; tag < kT; tag++) {
        float4 w0 = *(const float4*)(Wt + tag * 2 * kH + lane * 4);
        float4 w1 = *(const float4*)(Wt + tag * 2 * kH + kH + lane * 4);
        float p = a.x * w0.x + a.y * w0.y + a.z * w0.z + a.w * w0.w
                + cc.x * w1.x + cc.y * w1.y + cc.z * w1.z + cc.w * w1.w;
        p += __shfl_xor_sync(0xffffffffu, p, 16);
        p += __shfl_xor_sync(0xffffffffu, p, 8);
        p += __shfl_xor_sync(0xffffffffu, p, 4);
        p += __shfl_xor_sync(0xffffffffu, p, 2);
        p += __shfl_xor_sync(0xffffffffu, p, 1);
        if (lane == 0) g_feats[(size_t)lb * kT + tag] = p + bt[tag];
    }
}

// ---------------- K5: CRF forward scan + gold score ----------------
__global__ __launch_bounds__(512) void k_crf(const int* __restrict__ tags,
                                             const int* __restrict__ mask,
                                             const float* __restrict__ tr,
                                             float* __restrict__ out) {
    __shared__ float fwd_s[kB];
    __shared__ float gold_s[kB];
    const int tid = threadIdx.x;
    const int w = tid >> 5, lane = tid & 31;

    if (w < 8) {
        const int bi = lane >> 3;
        const int i  = lane & 7;
        const int b  = w * 4 + bi;
        const int ie = (i < kT) ? i : (kT - 1);
        const int base = lane & 24;

        float tr0 = tr[ie * kT + 0], tr1 = tr[ie * kT + 1], tr2 = tr[ie * kT + 2];
        float tr3 = tr[ie * kT + 3], tr4 = tr[ie * kT + 4];
        float alpha = (i == START) ? 0.0f : -10000.0f;
        const int mb = mask[b];
        float amask = 0.0f;

        for (int l = 1; l <= kL - 2; l++) {
            float f = g_feats[((size_t)l * kB + b) * kT + ie];
            float a0 = __shfl_sync(0xffffffffu, alpha, base + 0);
            float a1 = __shfl_sync(0xffffffffu, alpha, base + 1);
            float a2 = __shfl_sync(0xffffffffu, alpha, base + 2);
            float a3 = __shfl_sync(0xffffffffu, alpha, base + 3);
            float a4 = __shfl_sync(0xffffffffu, alpha, base + 4);
            float v0 = a0 + tr0, v1 = a1 + tr1, v2 = a2 + tr2;
            float v3 = a3 + tr3, v4 = a4 + tr4;
            float m = fmaxf(fmaxf(fmaxf(v0, v1), fmaxf(v2, v3)), v4);
            float ssum = __expf(v0 - m) + __expf(v1 - m) + __expf(v2 - m)
                       + __expf(v3 - m) + __expf(v4 - m);
            alpha = f + m + __logf(ssum);
            if (l == mb) amask = alpha;
        }
        float t0 = __shfl_sync(0xffffffffu, amask, base + 0) + tr[STOP * kT + 0];
        float t1 = __shfl_sync(0xffffffffu, amask, base + 1) + tr[STOP * kT + 1];
        float t2 = __shfl_sync(0xffffffffu, amask, base + 2) + tr[STOP * kT + 2];
        float t3 = __shfl_sync(0xffffffffu, amask, base + 3) + tr[STOP * kT + 3];
        float t4 = __shfl_sync(0xffffffffu, amask, base + 4) + tr[STOP * kT + 4];
        float m = fmaxf(fmaxf(fmaxf(t0, t1), fmaxf(t2, t3)), t4);
        float ssum = __expf(t0 - m) + __expf(t1 - m) + __expf(t2 - m)
                   + __expf(t3 - m) + __expf(t4 - m);
        if (i == 0) fwd_s[b] = m + __logf(ssum);
    } else if (w < 16) {
        const int b = (w - 8) * 4 + (lane >> 3);
        const int lp = lane & 7;
        const int mb = mask[b];
        float s = 0.0f;
        for (int p = lp; p < mb; p += 8) {
            int tp = tags[b * kL + p];
            int tn = tags[b * kL + p + 1];
            s += tr[tn * kT + tp] + g_feats[((size_t)(p + 1) * kB + b) * kT + tn];
        }
        s += __shfl_xor_sync(0xffffffffu, s, 4);
        s += __shfl_xor_sync(0xffffffffu, s, 2);
        s += __shfl_xor_sync(0xffffffffu, s, 1);
        if (lp == 0) gold_s[b] = s + tr[STOP * kT + tags[b * kL + mb]];
    }
    __syncthreads();
    if (tid == 0) {
        float fs = 0.0f, gs = 0.0f;
        for (int bb = 0; bb < kB; bb++) { fs += fwd_s[bb]; gs += gold_s[bb]; }
        out[0] = (fs - gs) * (1.0f / kB);
    }
}

// ---------------- launch ----------------
extern "C" void kernel_launch(void* const* d_in, const int* in_sizes, int n_in,
                              void* d_out, int out_size) {
    const int*   sentence = (const int*)d_in[0];
    const int*   tags     = (const int*)d_in[1];
    const int*   mask     = (const int*)d_in[2];
    const float* embed    = (const float*)d_in[3];
    const float* Wih_f    = (const float*)d_in[4];
    const float* Whh_f    = (const float*)d_in[5];
    const float* b_f      = (const float*)d_in[6];
    const float* Wih_b    = (const float*)d_in[7];
    const float* Whh_b    = (const float*)d_in[8];
    const float* b_b      = (const float*)d_in[9];
    const float* W_tag    = (const float*)d_in[10];
    const float* b_tag    = (const float*)d_in[11];
    const float* trans    = (const float*)d_in[12];
    const float* h0       = (const float*)d_in[13];
    const float* c0       = (const float*)d_in[14];
    (void)in_sizes; (void)n_in; (void)out_size;

    cudaFuncSetAttribute(k_lstm, cudaFuncAttributeMaxDynamicSharedMemorySize, LSTM_SMEM);
    cudaFuncSetAttribute(k_gemm_mma, cudaFuncAttributeMaxDynamicSharedMemorySize, GEMM_SMEM);

    k_gather<<<kL * kB, 64>>>(sentence, embed);
    k_wconv<<<kN, kEMB>>>(Wih_f, Wih_b);

    dim3 gg(kN / 128, (kL * kB) / 128);   // (8, 128)
    k_gemm_mma<<<gg, 256, GEMM_SMEM>>>(b_f, b_b);

    k_lstm<<<64, 512, LSTM_SMEM>>>(Whh_f, Whh_b, h0, c0);

    k_feats<<<(kL * kB) / 8, 256>>>(W_tag, b_tag);

    k_crf<<<1, 512>>>(tags, mask, trans, (float*)d_out);
}

// round 9
// speedup vs baseline: 1.5773x; 1.2217x over previous
#include <cuda_runtime.h>
#include <cuda_bf16.h>
#include <cstdint>

// ---------------- problem constants ----------------
constexpr int kL   = 512;
constexpr int kB   = 32;
constexpr int kEMB = 256;
constexpr int kH   = 128;   // per-direction hidden
constexpr int kG   = 512;   // 4*kH gate rows per direction
constexpr int kN   = 1024;  // both directions' gates
constexpr int kT   = 5;
constexpr int START = 3;
constexpr int STOP  = 4;

// ---------------- scratch (device globals; no allocs allowed) ----------------
__device__ __nv_bfloat16 g_xh[kL * kB * kEMB];   // x hi (bf16)
__device__ __nv_bfloat16 g_xl[kL * kB * kEMB];   // x lo (bf16 residual)
__device__ __nv_bfloat16 g_wh[kN * kEMB];        // [Wih_f;Wih_b] hi
__device__ __nv_bfloat16 g_wl[kN * kEMB];        // [Wih_f;Wih_b] lo
__device__ float g_gates[kL * kB * kN];          // (l,b,[fwd|bwd] gates)
__device__ float g_h[2 * kL * kB * kH];          // (dir,l,b,j)
__device__ float g_feats[kL * kB * kT];          // (l,b,tag)

// ---------------- small helpers ----------------
__device__ __forceinline__ float tanhapx(float x) {
    float y;
    asm("tanh.approx.f32 %0, %1;" : "=f"(y) : "f"(x));
    return y;
}
__device__ __forceinline__ float sigapx(float x) {
    return 0.5f * tanhapx(0.5f * x) + 0.5f;
}
__device__ __forceinline__ uint32_t smem_u32(const void* p) {
    uint32_t a;
    asm("{ .reg .u64 t; cvta.to.shared.u64 t, %1; cvt.u32.u64 %0, t; }" : "=r"(a) : "l"(p));
    return a;
}
__device__ __forceinline__ uint32_t swz128(uint32_t off) {
    return off ^ ((off >> 3) & 0x70);
}
__device__ __forceinline__ void cpasync16(uint32_t dst, const void* src) {
    asm volatile("cp.async.cg.shared.global [%0], [%1], 16;" :: "r"(dst), "l"(src));
}
__device__ __forceinline__ void ldsm4(uint32_t* r, uint32_t addr) {
    asm volatile("ldmatrix.sync.aligned.m8n8.x4.shared.b16 {%0,%1,%2,%3}, [%4];"
                 : "=r"(r[0]), "=r"(r[1]), "=r"(r[2]), "=r"(r[3]) : "r"(addr));
}
__device__ __forceinline__ void mma16816(float* d, const uint32_t* a, uint32_t b0, uint32_t b1) {
    asm volatile("mma.sync.aligned.m16n8k16.row.col.f32.bf16.bf16.f32 "
                 "{%0,%1,%2,%3}, {%4,%5,%6,%7}, {%8,%9}, {%0,%1,%2,%3};"
                 : "+f"(d[0]), "+f"(d[1]), "+f"(d[2]), "+f"(d[3])
                 : "r"(a[0]), "r"(a[1]), "r"(a[2]), "r"(a[3]), "r"(b0), "r"(b1));
}
// bf16x2 pack: first arg -> upper half, second -> lower half
__device__ __forceinline__ uint32_t bfpack(float hi, float lo) {
    uint32_t d;
    asm("cvt.rn.bf16x2.f32 %0, %1, %2;" : "=r"(d) : "f"(hi), "f"(lo));
    return d;
}
__device__ __forceinline__ uint32_t hfma2bf(uint32_t a, uint32_t b, uint32_t c) {
    uint32_t d;
    asm("fma.rn.bf16x2 %0, %1, %2, %3;" : "=r"(d) : "r"(a), "r"(b), "r"(c));
    return d;
}
// unpack bf16x2 -> two fp32 via bit ops (ALU pipe)
__device__ __forceinline__ float bflo(uint32_t v) { return __uint_as_float(v << 16); }
__device__ __forceinline__ float bfhi(uint32_t v) { return __uint_as_float(v & 0xffff0000u); }

// ---------------- K1: embedding gather + bf16 hi/lo split ----------------
__global__ void k_gather(const int* __restrict__ sent, const float* __restrict__ embed) {
    int lb = blockIdx.x;              // l*32 + b
    int l = lb >> 5, b = lb & 31;
    int tok = sent[b * kL + l];
    float4 v = ((const float4*)(embed + (size_t)tok * kEMB))[threadIdx.x];
    float xs[4] = {v.x, v.y, v.z, v.w};
    ushort4 hp, lp;
    unsigned short* hpp = (unsigned short*)&hp;
    unsigned short* lpp = (unsigned short*)&lp;
#pragma unroll
    for (int i = 0; i < 4; i++) {
        __nv_bfloat16 h = __float2bfloat16_rn(xs[i]);
        __nv_bfloat16 lo = __float2bfloat16_rn(xs[i] - __bfloat162float(h));
        hpp[i] = *(unsigned short*)&h;
        lpp[i] = *(unsigned short*)&lo;
    }
    size_t o = (size_t)lb * kEMB + threadIdx.x * 4;
    *(ushort4*)(g_xh + o) = hp;
    *(ushort4*)(g_xl + o) = lp;
}

// ---------------- K1b: weight bf16 hi/lo split ----------------
__global__ void k_wconv(const float* __restrict__ Wf, const float* __restrict__ Wb) {
    int row = blockIdx.x;             // 0..1023
    int k = threadIdx.x;              // 0..255
    float v = (row < kG) ? Wf[(size_t)row * kEMB + k] : Wb[(size_t)(row - kG) * kEMB + k];
    __nv_bfloat16 h = __float2bfloat16_rn(v);
    __nv_bfloat16 lo = __float2bfloat16_rn(v - __bfloat162float(h));
    g_wh[(size_t)row * kEMB + k] = h;
    g_wl[(size_t)row * kEMB + k] = lo;
}

// ---------------- K2: mma.sync bf16 GEMM  g_gates = x @ W^T + bias ----------------
constexpr int GKC = 64;                 // K per chunk (bf16)
constexpr int NCHUNK = 12;              // 768 / 64
constexpr int GBUF = 32768;             // A(16KB)+B(16KB) per buffer
constexpr int GEMM_SMEM = 2 * GBUF;     // 64 KB

__device__ __forceinline__ void ld_chunk(uint32_t sbase, int ck, int buf, int m0, int n0) {
    const int tid = threadIdx.x;
    const int seg = ck >> 2;
    const int koff = (ck & 3) * GKC;
    const __nv_bfloat16* Ag = (seg < 2) ? g_xh : g_xl;
    const __nv_bfloat16* Bg = (seg == 1) ? g_wl : g_wh;
    const uint32_t abase = sbase + buf * GBUF;
    const uint32_t bbase = abase + 16384;
#pragma unroll
    for (int i = 0; i < 4; i++) {
        int idx = i * 256 + tid;        // 0..1023 : 128 rows x 8 16B-chunks
        int r = idx >> 3;
        int c8 = idx & 7;               // 16B chunk within 128B row
        uint32_t so = swz128((uint32_t)(r * 128 + c8 * 16));
        cpasync16(abase + so, Ag + (size_t)(m0 + r) * kEMB + koff + c8 * 8);
        cpasync16(bbase + so, Bg + (size_t)(n0 + r) * kEMB + koff + c8 * 8);
    }
}

__global__ __launch_bounds__(256, 2) void k_gemm_mma(const float* __restrict__ biasf,
                                                     const float* __restrict__ biasb) {
    extern __shared__ __align__(1024) char smem[];
    const uint32_t sbase = smem_u32(smem);
    const int tid = threadIdx.x;
    const int wid = tid >> 5;
    const int lane = tid & 31;
    const int m0 = blockIdx.y * 128;
    const int n0 = blockIdx.x * 128;
    const int wm = (wid & 1) * 64;      // warp M offset in tile
    const int wn = (wid >> 1) * 32;     // warp N offset in tile

    float acc[4][4][4];
#pragma unroll
    for (int a = 0; a < 4; a++)
#pragma unroll
        for (int b = 0; b < 4; b++)
#pragma unroll
            for (int c = 0; c < 4; c++) acc[a][b][c] = 0.0f;

    ld_chunk(sbase, 0, 0, m0, n0);
    asm volatile("cp.async.commit_group;");

    const int rbase = (lane & 7) + ((lane >> 3) & 1) * 8;
    const int cext = (lane >> 4) * 16;

    for (int ck = 0; ck < NCHUNK; ck++) {
        if (ck + 1 < NCHUNK) ld_chunk(sbase, ck + 1, (ck + 1) & 1, m0, n0);
        asm volatile("cp.async.commit_group;");
        asm volatile("cp.async.wait_group 1;");
        __syncthreads();

        const uint32_t abuf = sbase + (ck & 1) * GBUF;
        const uint32_t bbuf = abuf + 16384;
#pragma unroll
        for (int k16 = 0; k16 < 4; k16++) {
            const int cb = k16 * 32 + cext;
            uint32_t a[4][4];
#pragma unroll
            for (int mi = 0; mi < 4; mi++)
                ldsm4(a[mi], abuf + swz128((uint32_t)((wm + mi * 16 + rbase) * 128 + cb)));
            uint32_t bfr[2][4];
#pragma unroll
            for (int p = 0; p < 2; p++)
                ldsm4(bfr[p], bbuf + swz128((uint32_t)((wn + p * 16 + rbase) * 128 + cb)));
#pragma unroll
            for (int mi = 0; mi < 4; mi++)
#pragma unroll
                for (int nj = 0; nj < 4; nj++)
                    mma16816(acc[mi][nj], a[mi], bfr[nj >> 1][nj & 1], bfr[nj >> 1][(nj & 1) + 2]);
        }
        __syncthreads();
    }

    // epilogue + bias
#pragma unroll
    for (int mi = 0; mi < 4; mi++) {
        int row = m0 + wm + mi * 16 + (lane >> 2);
#pragma unroll
        for (int nj = 0; nj < 4; nj++) {
            int col = n0 + wn + nj * 8 + (lane & 3) * 2;
            float bx = (col < kG) ? biasf[col] : biasb[col - kG];
            float by = (col + 1 < kG) ? biasf[col + 1] : biasb[col + 1 - kG];
            float2 v0 = make_float2(acc[mi][nj][0] + bx, acc[mi][nj][1] + by);
            float2 v1 = make_float2(acc[mi][nj][2] + bx, acc[mi][nj][3] + by);
            *(float2*)(g_gates + (size_t)row * kN + col) = v0;
            *(float2*)(g_gates + (size_t)(row + 8) * kN + col) = v1;
        }
    }
}

// ---------------- K3: LSTM recurrence (all-register bf16x2 weights) ----------------
// 64 blocks (chain = dir*32+b), 512 threads, thread t owns gate row t.
// Whh row (128 cols) fully register-resident as 64 bf16x2 regs.
// h broadcast from smem as 64 bf16x2 (16 LDS.128/thread, conflict-free).
// Dot in 4 independent bf16x2 accumulators (16 terms each), combined + pre in fp32.
__global__ __launch_bounds__(512, 1) void k_lstm(const float* __restrict__ Whh_f,
                                                 const float* __restrict__ Whh_b,
                                                 const float* __restrict__ h0,
                                                 const float* __restrict__ c0) {
    __shared__ float g_s[512];
    __shared__ __align__(16) uint32_t h_bf[64];

    const int t   = threadIdx.x;
    const int blk = blockIdx.x;
    const int dir = blk >> 5;
    const int b   = blk & 31;
    const float* Whh = dir ? Whh_b : Whh_f;

    // pack full weight row into registers: wreg[i] = (col 2i+1 | col 2i)
    uint32_t wreg[64];
#pragma unroll
    for (int i = 0; i < 64; i++) {
        float2 wv = *(const float2*)(Whh + (size_t)t * kH + 2 * i);
        wreg[i] = bfpack(wv.y, wv.x);
    }

    float c = 0.0f;
    if (t < kH) {
        c = c0[(dir * kB + b) * kH + t];
        float hini = h0[(dir * kB + b) * kH + t];
        float hn = __shfl_down_sync(0xffffffffu, hini, 1);
        if (!(t & 1)) h_bf[t >> 1] = bfpack(hn, hini);
    }
    __syncthreads();

    int l = dir ? (kL - 1) : 0;
    const int step = dir ? -1 : 1;
    const int gofs = dir ? kG : 0;

    float pre = g_gates[((size_t)l * kB + b) * kN + gofs + t];

    for (int s = 0; s < kL; s++) {
        int ln = l + step;
        int lnc = min(max(ln, 0), kL - 1);
        float pre_next = g_gates[((size_t)lnc * kB + b) * kN + gofs + t];

        uint32_t a0 = 0u, a1 = 0u, a2 = 0u, a3 = 0u;
        const uint4* hb = (const uint4*)h_bf;
#pragma unroll
        for (int i = 0; i < 16; i++) {
            uint4 hv = hb[i];
            a0 = hfma2bf(wreg[4 * i + 0], hv.x, a0);
            a1 = hfma2bf(wreg[4 * i + 1], hv.y, a1);
            a2 = hfma2bf(wreg[4 * i + 2], hv.z, a2);
            a3 = hfma2bf(wreg[4 * i + 3], hv.w, a3);
        }
        float v = pre + ((bflo(a0) + bfhi(a0)) + (bflo(a1) + bfhi(a1)))
                      + ((bflo(a2) + bfhi(a2)) + (bflo(a3) + bfhi(a3)));
        g_s[t] = v;
        __syncthreads();

        if (t < kH) {
            float gi = g_s[t];
            float gf = g_s[kH + t];
            float gg = g_s[2 * kH + t];
            float go = g_s[3 * kH + t];
            c = sigapx(gf) * c + sigapx(gi) * tanhapx(gg);
            float h = sigapx(go) * tanhapx(c);
            float hn = __shfl_down_sync(0xffffffffu, h, 1);
            if (!(t & 1)) h_bf[t >> 1] = bfpack(hn, h);
            g_h[(((size_t)dir * kL + l) * kB + b) * kH + t] = h;
        }
        __syncthreads();

        pre = pre_next;
        l = ln;
    }
}

// ---------------- K4: feats = concat(hf,hb) @ W_tag^T + b_tag ----------------
__global__ void k_feats(const float* __restrict__ Wt, const float* __restrict__ bt) {
    int lb = blockIdx.x * 8 + (threadIdx.x >> 5);
    int lane = threadIdx.x & 31;
    const float4* hbase = (const float4*)g_h;
    float4 a = hbase[(size_t)lb * 32 + lane];
    float4 cc = hbase[(size_t)kL * kB * 32 + (size_t)lb * 32 + lane];
#pragma unroll
    for (int tag = 0; tag < kT; tag++) {
        float4 w0 = *(const float4*)(Wt + tag * 2 * kH + lane * 4);
        float4 w1 = *(const float4*)(Wt + tag * 2 * kH + kH + lane * 4);
        float p = a.x * w0.x + a.y * w0.y + a.z * w0.z + a.w * w0.w
                + cc.x * w1.x + cc.y * w1.y + cc.z * w1.z + cc.w * w1.w;
        p += __shfl_xor_sync(0xffffffffu, p, 16);
        p += __shfl_xor_sync(0xffffffffu, p, 8);
        p += __shfl_xor_sync(0xffffffffu, p, 4);
        p += __shfl_xor_sync(0xffffffffu, p, 2);
        p += __shfl_xor_sync(0xffffffffu, p, 1);
        if (lane == 0) g_feats[(size_t)lb * kT + tag] = p + bt[tag];
    }
}

// ---------------- K5: CRF forward scan + gold score ----------------
__global__ __launch_bounds__(512) void k_crf(const int* __restrict__ tags,
                                             const int* __restrict__ mask,
                                             const float* __restrict__ tr,
                                             float* __restrict__ out) {
    __shared__ float fwd_s[kB];
    __shared__ float gold_s[kB];
    const int tid = threadIdx.x;
    const int w = tid >> 5, lane = tid & 31;

    if (w < 8) {
        const int bi = lane >> 3;
        const int i  = lane & 7;
        const int b  = w * 4 + bi;
        const int ie = (i < kT) ? i : (kT - 1);
        const int base = lane & 24;

        float tr0 = tr[ie * kT + 0], tr1 = tr[ie * kT + 1], tr2 = tr[ie * kT + 2];
        float tr3 = tr[ie * kT + 3], tr4 = tr[ie * kT + 4];
        float alpha = (i == START) ? 0.0f : -10000.0f;
        const int mb = mask[b];
        float amask = 0.0f;

        for (int l = 1; l <= kL - 2; l++) {
            float f = g_feats[((size_t)l * kB + b) * kT + ie];
            float a0 = __shfl_sync(0xffffffffu, alpha, base + 0);
            float a1 = __shfl_sync(0xffffffffu, alpha, base + 1);
            float a2 = __shfl_sync(0xffffffffu, alpha, base + 2);
            float a3 = __shfl_sync(0xffffffffu, alpha, base + 3);
            float a4 = __shfl_sync(0xffffffffu, alpha, base + 4);
            float v0 = a0 + tr0, v1 = a1 + tr1, v2 = a2 + tr2;
            float v3 = a3 + tr3, v4 = a4 + tr4;
            float m = fmaxf(fmaxf(fmaxf(v0, v1), fmaxf(v2, v3)), v4);
            float ssum = __expf(v0 - m) + __expf(v1 - m) + __expf(v2 - m)
                       + __expf(v3 - m) + __expf(v4 - m);
            alpha = f + m + __logf(ssum);
            if (l == mb) amask = alpha;
        }
        float t0 = __shfl_sync(0xffffffffu, amask, base + 0) + tr[STOP * kT + 0];
        float t1 = __shfl_sync(0xffffffffu, amask, base + 1) + tr[STOP * kT + 1];
        float t2 = __shfl_sync(0xffffffffu, amask, base + 2) + tr[STOP * kT + 2];
        float t3 = __shfl_sync(0xffffffffu, amask, base + 3) + tr[STOP * kT + 3];
        float t4 = __shfl_sync(0xffffffffu, amask, base + 4) + tr[STOP * kT + 4];
        float m = fmaxf(fmaxf(fmaxf(t0, t1), fmaxf(t2, t3)), t4);
        float ssum = __expf(t0 - m) + __expf(t1 - m) + __expf(t2 - m)
                   + __expf(t3 - m) + __expf(t4 - m);
        if (i == 0) fwd_s[b] = m + __logf(ssum);
    } else if (w < 16) {
        const int b = (w - 8) * 4 + (lane >> 3);
        const int lp = lane & 7;
        const int mb = mask[b];
        float s = 0.0f;
        for (int p = lp; p < mb; p += 8) {
            int tp = tags[b * kL + p];
            int tn = tags[b * kL + p + 1];
            s += tr[tn * kT + tp] + g_feats[((size_t)(p + 1) * kB + b) * kT + tn];
        }
        s += __shfl_xor_sync(0xffffffffu, s, 4);
        s += __shfl_xor_sync(0xffffffffu, s, 2);
        s += __shfl_xor_sync(0xffffffffu, s, 1);
        if (lp == 0) gold_s[b] = s + tr[STOP * kT + tags[b * kL + mb]];
    }
    __syncthreads();
    if (tid == 0) {
        float fs = 0.0f, gs = 0.0f;
        for (int bb = 0; bb < kB; bb++) { fs += fwd_s[bb]; gs += gold_s[bb]; }
        out[0] = (fs - gs) * (1.0f / kB);
    }
}

// ---------------- launch ----------------
extern "C" void kernel_launch(void* const* d_in, const int* in_sizes, int n_in,
                              void* d_out, int out_size) {
    const int*   sentence = (const int*)d_in[0];
    const int*   tags     = (const int*)d_in[1];
    const int*   mask     = (const int*)d_in[2];
    const float* embed    = (const float*)d_in[3];
    const float* Wih_f    = (const float*)d_in[4];
    const float* Whh_f    = (const float*)d_in[5];
    const float* b_f      = (const float*)d_in[6];
    const float* Wih_b    = (const float*)d_in[7];
    const float* Whh_b    = (const float*)d_in[8];
    const float* b_b      = (const float*)d_in[9];
    const float* W_tag    = (const float*)d_in[10];
    const float* b_tag    = (const float*)d_in[11];
    const float* trans    = (const float*)d_in[12];
    const float* h0       = (const float*)d_in[13];
    const float* c0       = (const float*)d_in[14];
    (void)in_sizes; (void)n_in; (void)out_size;

    cudaFuncSetAttribute(k_gemm_mma, cudaFuncAttributeMaxDynamicSharedMemorySize, GEMM_SMEM);

    k_gather<<<kL * kB, 64>>>(sentence, embed);
    k_wconv<<<kN, kEMB>>>(Wih_f, Wih_b);

    dim3 gg(kN / 128, (kL * kB) / 128);   // (8, 128)
    k_gemm_mma<<<gg, 256, GEMM_SMEM>>>(b_f, b_b);

    k_lstm<<<64, 512>>>(Whh_f, Whh_b, h0, c0);

    k_feats<<<(kL * kB) / 8, 256>>>(W_tag, b_tag);

    k_crf<<<1, 512>>>(tags, mask, trans, (float*)d_out);
}

// round 10
// speedup vs baseline: 1.8243x; 1.1567x over previous
#include <cuda_runtime.h>
#include <cuda_bf16.h>
#include <cstdint>

// ---------------- problem constants ----------------
constexpr int kL   = 512;
constexpr int kB   = 32;
constexpr int kEMB = 256;
constexpr int kH   = 128;   // per-direction hidden
constexpr int kG   = 512;   // 4*kH gate rows per direction
constexpr int kN   = 1024;  // both directions' gates
constexpr int kT   = 5;
constexpr int START = 3;
constexpr int STOP  = 4;

// ---------------- scratch (device globals; no allocs allowed) ----------------
__device__ __nv_bfloat16 g_xh[kL * kB * kEMB];   // x hi (bf16)
__device__ __nv_bfloat16 g_xl[kL * kB * kEMB];   // x lo (bf16 residual)
__device__ __nv_bfloat16 g_wh[kN * kEMB];        // [Wih_f;Wih_b] hi
__device__ float g_gates[kL * kB * kN];          // (l,b,[fwd|bwd] gates)
__device__ float g_h[2 * kL * kB * kH];          // (dir,l,b,j)
__device__ float g_feats[kL * kB * kT];          // (l,b,tag)

// ---------------- small helpers ----------------
__device__ __forceinline__ float tanhapx(float x) {
    float y;
    asm("tanh.approx.f32 %0, %1;" : "=f"(y) : "f"(x));
    return y;
}
__device__ __forceinline__ float sigapx(float x) {
    return 0.5f * tanhapx(0.5f * x) + 0.5f;
}
__device__ __forceinline__ uint32_t smem_u32(const void* p) {
    uint32_t a;
    asm("{ .reg .u64 t; cvta.to.shared.u64 t, %1; cvt.u32.u64 %0, t; }" : "=r"(a) : "l"(p));
    return a;
}
__device__ __forceinline__ uint32_t swz128(uint32_t off) {
    return off ^ ((off >> 3) & 0x70);
}
__device__ __forceinline__ void cpasync16(uint32_t dst, const void* src) {
    asm volatile("cp.async.cg.shared.global [%0], [%1], 16;" :: "r"(dst), "l"(src));
}
__device__ __forceinline__ void ldsm4(uint32_t* r, uint32_t addr) {
    asm volatile("ldmatrix.sync.aligned.m8n8.x4.shared.b16 {%0,%1,%2,%3}, [%4];"
                 : "=r"(r[0]), "=r"(r[1]), "=r"(r[2]), "=r"(r[3]) : "r"(addr));
}
__device__ __forceinline__ void mma16816(float* d, const uint32_t* a, uint32_t b0, uint32_t b1) {
    asm volatile("mma.sync.aligned.m16n8k16.row.col.f32.bf16.bf16.f32 "
                 "{%0,%1,%2,%3}, {%4,%5,%6,%7}, {%8,%9}, {%0,%1,%2,%3};"
                 : "+f"(d[0]), "+f"(d[1]), "+f"(d[2]), "+f"(d[3])
                 : "r"(a[0]), "r"(a[1]), "r"(a[2]), "r"(a[3]), "r"(b0), "r"(b1));
}
// bf16x2 pack: first arg -> upper half, second -> lower half
__device__ __forceinline__ uint32_t bfpack(float hi, float lo) {
    uint32_t d;
    asm("cvt.rn.bf16x2.f32 %0, %1, %2;" : "=r"(d) : "f"(hi), "f"(lo));
    return d;
}
__device__ __forceinline__ uint32_t hfma2bf(uint32_t a, uint32_t b, uint32_t c) {
    uint32_t d;
    asm("fma.rn.bf16x2 %0, %1, %2, %3;" : "=r"(d) : "r"(a), "r"(b), "r"(c));
    return d;
}
// unpack bf16x2 -> two fp32 via bit ops (ALU pipe)
__device__ __forceinline__ float bflo(uint32_t v) { return __uint_as_float(v << 16); }
__device__ __forceinline__ float bfhi(uint32_t v) { return __uint_as_float(v & 0xffff0000u); }

// ---------------- K1: embedding gather + bf16 hi/lo split ----------------
__global__ void k_gather(const int* __restrict__ sent, const float* __restrict__ embed) {
    int lb = blockIdx.x;              // l*32 + b
    int l = lb >> 5, b = lb & 31;
    int tok = sent[b * kL + l];
    float4 v = ((const float4*)(embed + (size_t)tok * kEMB))[threadIdx.x];
    float xs[4] = {v.x, v.y, v.z, v.w};
    ushort4 hp, lp;
    unsigned short* hpp = (unsigned short*)&hp;
    unsigned short* lpp = (unsigned short*)&lp;
#pragma unroll
    for (int i = 0; i < 4; i++) {
        __nv_bfloat16 h = __float2bfloat16_rn(xs[i]);
        __nv_bfloat16 lo = __float2bfloat16_rn(xs[i] - __bfloat162float(h));
        hpp[i] = *(unsigned short*)&h;
        lpp[i] = *(unsigned short*)&lo;
    }
    size_t o = (size_t)lb * kEMB + threadIdx.x * 4;
    *(ushort4*)(g_xh + o) = hp;
    *(ushort4*)(g_xl + o) = lp;
}

// ---------------- K1b: weight bf16 conversion (hi only) ----------------
__global__ void k_wconv(const float* __restrict__ Wf, const float* __restrict__ Wb) {
    int row = blockIdx.x;             // 0..1023
    int k = threadIdx.x;              // 0..255
    float v = (row < kG) ? Wf[(size_t)row * kEMB + k] : Wb[(size_t)(row - kG) * kEMB + k];
    g_wh[(size_t)row * kEMB + k] = __float2bfloat16_rn(v);
}

// ---------------- K2: mma.sync bf16 GEMM  g_gates = x @ W^T + bias ----------------
// Effective K = 512 = 2 segments of 256: (xh,wh), (xl,wh).
constexpr int GKC = 64;                 // K per chunk (bf16)
constexpr int NCHUNK = 8;               // 512 / 64
constexpr int GBUF = 32768;             // A(16KB)+B(16KB) per buffer
constexpr int GEMM_SMEM = 2 * GBUF;     // 64 KB

__device__ __forceinline__ void ld_chunk(uint32_t sbase, int ck, int buf, int m0, int n0) {
    const int tid = threadIdx.x;
    const int seg = ck >> 2;
    const int koff = (ck & 3) * GKC;
    const __nv_bfloat16* Ag = (seg == 0) ? g_xh : g_xl;
    const __nv_bfloat16* Bg = g_wh;
    const uint32_t abase = sbase + buf * GBUF;
    const uint32_t bbase = abase + 16384;
#pragma unroll
    for (int i = 0; i < 4; i++) {
        int idx = i * 256 + tid;        // 0..1023 : 128 rows x 8 16B-chunks
        int r = idx >> 3;
        int c8 = idx & 7;               // 16B chunk within 128B row
        uint32_t so = swz128((uint32_t)(r * 128 + c8 * 16));
        cpasync16(abase + so, Ag + (size_t)(m0 + r) * kEMB + koff + c8 * 8);
        cpasync16(bbase + so, Bg + (size_t)(n0 + r) * kEMB + koff + c8 * 8);
    }
}

__global__ __launch_bounds__(256, 2) void k_gemm_mma(const float* __restrict__ biasf,
                                                     const float* __restrict__ biasb) {
    extern __shared__ __align__(1024) char smem[];
    const uint32_t sbase = smem_u32(smem);
    const int tid = threadIdx.x;
    const int wid = tid >> 5;
    const int lane = tid & 31;
    const int m0 = blockIdx.y * 128;
    const int n0 = blockIdx.x * 128;
    const int wm = (wid & 1) * 64;      // warp M offset in tile
    const int wn = (wid >> 1) * 32;     // warp N offset in tile

    float acc[4][4][4];
#pragma unroll
    for (int a = 0; a < 4; a++)
#pragma unroll
        for (int b = 0; b < 4; b++)
#pragma unroll
            for (int c = 0; c < 4; c++) acc[a][b][c] = 0.0f;

    ld_chunk(sbase, 0, 0, m0, n0);
    asm volatile("cp.async.commit_group;");

    const int rbase = (lane & 7) + ((lane >> 3) & 1) * 8;
    const int cext = (lane >> 4) * 16;

    for (int ck = 0; ck < NCHUNK; ck++) {
        if (ck + 1 < NCHUNK) ld_chunk(sbase, ck + 1, (ck + 1) & 1, m0, n0);
        asm volatile("cp.async.commit_group;");
        asm volatile("cp.async.wait_group 1;");
        __syncthreads();

        const uint32_t abuf = sbase + (ck & 1) * GBUF;
        const uint32_t bbuf = abuf + 16384;
#pragma unroll
        for (int k16 = 0; k16 < 4; k16++) {
            const int cb = k16 * 32 + cext;
            uint32_t a[4][4];
#pragma unroll
            for (int mi = 0; mi < 4; mi++)
                ldsm4(a[mi], abuf + swz128((uint32_t)((wm + mi * 16 + rbase) * 128 + cb)));
            uint32_t bfr[2][4];
#pragma unroll
            for (int p = 0; p < 2; p++)
                ldsm4(bfr[p], bbuf + swz128((uint32_t)((wn + p * 16 + rbase) * 128 + cb)));
#pragma unroll
            for (int mi = 0; mi < 4; mi++)
#pragma unroll
                for (int nj = 0; nj < 4; nj++)
                    mma16816(acc[mi][nj], a[mi], bfr[nj >> 1][nj & 1], bfr[nj >> 1][(nj & 1) + 2]);
        }
        __syncthreads();
    }

    // epilogue + bias
#pragma unroll
    for (int mi = 0; mi < 4; mi++) {
        int row = m0 + wm + mi * 16 + (lane >> 2);
#pragma unroll
        for (int nj = 0; nj < 4; nj++) {
            int col = n0 + wn + nj * 8 + (lane & 3) * 2;
            float bx = (col < kG) ? biasf[col] : biasb[col - kG];
            float by = (col + 1 < kG) ? biasf[col + 1] : biasb[col + 1 - kG];
            float2 v0 = make_float2(acc[mi][nj][0] + bx, acc[mi][nj][1] + by);
            float2 v1 = make_float2(acc[mi][nj][2] + bx, acc[mi][nj][3] + by);
            *(float2*)(g_gates + (size_t)row * kN + col) = v0;
            *(float2*)(g_gates + (size_t)(row + 8) * kN + col) = v1;
        }
    }
}

// ---------------- K3: LSTM recurrence (256 thr, 2 gate rows/thread) ----------------
// 64 blocks (chain = dir*32+b), 256 threads. Thread t owns gate rows t and t+256.
// All weights register-resident bf16x2 (128 regs); h broadcast from smem (16 LDS.128,
// reused by both rows). Reg budget at 256 thr = 256/thread, so no spills.
__global__ __launch_bounds__(256, 1) void k_lstm(const float* __restrict__ Whh_f,
                                                 const float* __restrict__ Whh_b,
                                                 const float* __restrict__ h0,
                                                 const float* __restrict__ c0) {
    __shared__ float g_s[512];
    __shared__ __align__(16) uint32_t h_bf[64];

    const int t   = threadIdx.x;        // 0..255
    const int blk = blockIdx.x;
    const int dir = blk >> 5;
    const int b   = blk & 31;
    const float* Whh = dir ? Whh_b : Whh_f;
    const int r0 = t;                   // gate rows owned by this thread
    const int r1 = t + 256;

    uint32_t w0[64], w1[64];
#pragma unroll
    for (int i = 0; i < 64; i++) {
        float2 a = *(const float2*)(Whh + (size_t)r0 * kH + 2 * i);
        float2 d = *(const float2*)(Whh + (size_t)r1 * kH + 2 * i);
        w0[i] = bfpack(a.y, a.x);
        w1[i] = bfpack(d.y, d.x);
    }

    float c = 0.0f;
    if (t < kH) {
        c = c0[(dir * kB + b) * kH + t];
        float hini = h0[(dir * kB + b) * kH + t];
        float hn = __shfl_down_sync(0xffffffffu, hini, 1);
        if (!(t & 1)) h_bf[t >> 1] = bfpack(hn, hini);
    }
    __syncthreads();

    int l = dir ? (kL - 1) : 0;
    const int step = dir ? -1 : 1;
    const int gofs = dir ? kG : 0;

    float pre0 = g_gates[((size_t)l * kB + b) * kN + gofs + r0];
    float pre1 = g_gates[((size_t)l * kB + b) * kN + gofs + r1];

    for (int s = 0; s < kL; s++) {
        int ln = l + step;
        int lnc = min(max(ln, 0), kL - 1);
        const float* gnext = g_gates + ((size_t)lnc * kB + b) * kN + gofs;
        float pn0 = gnext[r0];
        float pn1 = gnext[r1];

        uint32_t a0 = 0u, a1 = 0u, a2 = 0u, a3 = 0u;
        uint32_t d0 = 0u, d1 = 0u, d2 = 0u, d3 = 0u;
        const uint4* hb = (const uint4*)h_bf;
#pragma unroll
        for (int i = 0; i < 16; i++) {
            uint4 hv = hb[i];
            a0 = hfma2bf(w0[4 * i + 0], hv.x, a0);
            a1 = hfma2bf(w0[4 * i + 1], hv.y, a1);
            a2 = hfma2bf(w0[4 * i + 2], hv.z, a2);
            a3 = hfma2bf(w0[4 * i + 3], hv.w, a3);
            d0 = hfma2bf(w1[4 * i + 0], hv.x, d0);
            d1 = hfma2bf(w1[4 * i + 1], hv.y, d1);
            d2 = hfma2bf(w1[4 * i + 2], hv.z, d2);
            d3 = hfma2bf(w1[4 * i + 3], hv.w, d3);
        }
        g_s[r0] = pre0 + ((bflo(a0) + bfhi(a0)) + (bflo(a1) + bfhi(a1)))
                       + ((bflo(a2) + bfhi(a2)) + (bflo(a3) + bfhi(a3)));
        g_s[r1] = pre1 + ((bflo(d0) + bfhi(d0)) + (bflo(d1) + bfhi(d1)))
                       + ((bflo(d2) + bfhi(d2)) + (bflo(d3) + bfhi(d3)));
        __syncthreads();

        if (t < kH) {
            float gi = g_s[t];
            float gf = g_s[kH + t];
            float gg = g_s[2 * kH + t];
            float go = g_s[3 * kH + t];
            c = sigapx(gf) * c + sigapx(gi) * tanhapx(gg);
            float h = sigapx(go) * tanhapx(c);
            float hn = __shfl_down_sync(0xffffffffu, h, 1);
            if (!(t & 1)) h_bf[t >> 1] = bfpack(hn, h);
            g_h[(((size_t)dir * kL + l) * kB + b) * kH + t] = h;
        }
        __syncthreads();

        pre0 = pn0;
        pre1 = pn1;
        l = ln;
    }
}

// ---------------- K4: feats = concat(hf,hb) @ W_tag^T + b_tag ----------------
__global__ void k_feats(const float* __restrict__ Wt, const float* __restrict__ bt) {
    int lb = blockIdx.x * 8 + (threadIdx.x >> 5);
    int lane = threadIdx.x & 31;
    const float4* hbase = (const float4*)g_h;
    float4 a = hbase[(size_t)lb * 32 + lane];
    float4 cc = hbase[(size_t)kL * kB * 32 + (size_t)lb * 32 + lane];
#pragma unroll
    for (int tag = 0; tag < kT; tag++) {
        float4 w0 = *(const float4*)(Wt + tag * 2 * kH + lane * 4);
        float4 w1 = *(const float4*)(Wt + tag * 2 * kH + kH + lane * 4);
        float p = a.x * w0.x + a.y * w0.y + a.z * w0.z + a.w * w0.w
                + cc.x * w1.x + cc.y * w1.y + cc.z * w1.z + cc.w * w1.w;
        p += __shfl_xor_sync(0xffffffffu, p, 16);
        p += __shfl_xor_sync(0xffffffffu, p, 8);
        p += __shfl_xor_sync(0xffffffffu, p, 4);
        p += __shfl_xor_sync(0xffffffffu, p, 2);
        p += __shfl_xor_sync(0xffffffffu, p, 1);
        if (lane == 0) g_feats[(size_t)lb * kT + tag] = p + bt[tag];
    }
}

// ---------------- K5: CRF forward scan + gold score ----------------
__global__ __launch_bounds__(512) void k_crf(const int* __restrict__ tags,
                                             const int* __restrict__ mask,
                                             const float* __restrict__ tr,
                                             float* __restrict__ out) {
    __shared__ float fwd_s[kB];
    __shared__ float gold_s[kB];
    const int tid = threadIdx.x;
    const int w = tid >> 5, lane = tid & 31;

    if (w < 8) {
        const int bi = lane >> 3;
        const int i  = lane & 7;
        const int b  = w * 4 + bi;
        const int ie = (i < kT) ? i : (kT - 1);
        const int base = lane & 24;

        float tr0 = tr[ie * kT + 0], tr1 = tr[ie * kT + 1], tr2 = tr[ie * kT + 2];
        float tr3 = tr[ie * kT + 3], tr4 = tr[ie * kT + 4];
        float alpha = (i == START) ? 0.0f : -10000.0f;
        const int mb = mask[b];
        float amask = 0.0f;

        for (int l = 1; l <= kL - 2; l++) {
            float f = g_feats[((size_t)l * kB + b) * kT + ie];
            float a0 = __shfl_sync(0xffffffffu, alpha, base + 0);
            float a1 = __shfl_sync(0xffffffffu, alpha, base + 1);
            float a2 = __shfl_sync(0xffffffffu, alpha, base + 2);
            float a3 = __shfl_sync(0xffffffffu, alpha, base + 3);
            float a4 = __shfl_sync(0xffffffffu, alpha, base + 4);
            float v0 = a0 + tr0, v1 = a1 + tr1, v2 = a2 + tr2;
            float v3 = a3 + tr3, v4 = a4 + tr4;
            float m = fmaxf(fmaxf(fmaxf(v0, v1), fmaxf(v2, v3)), v4);
            float ssum = __expf(v0 - m) + __expf(v1 - m) + __expf(v2 - m)
                       + __expf(v3 - m) + __expf(v4 - m);
            alpha = f + m + __logf(ssum);
            if (l == mb) amask = alpha;
        }
        float t0 = __shfl_sync(0xffffffffu, amask, base + 0) + tr[STOP * kT + 0];
        float t1 = __shfl_sync(0xffffffffu, amask, base + 1) + tr[STOP * kT + 1];
        float t2 = __shfl_sync(0xffffffffu, amask, base + 2) + tr[STOP * kT + 2];
        float t3 = __shfl_sync(0xffffffffu, amask, base + 3) + tr[STOP * kT + 3];
        float t4 = __shfl_sync(0xffffffffu, amask, base + 4) + tr[STOP * kT + 4];
        float m = fmaxf(fmaxf(fmaxf(t0, t1), fmaxf(t2, t3)), t4);
        float ssum = __expf(t0 - m) + __expf(t1 - m) + __expf(t2 - m)
                   + __expf(t3 - m) + __expf(t4 - m);
        if (i == 0) fwd_s[b] = m + __logf(ssum);
    } else if (w < 16) {
        const int b = (w - 8) * 4 + (lane >> 3);
        const int lp = lane & 7;
        const int mb = mask[b];
        float s = 0.0f;
        for (int p = lp; p < mb; p += 8) {
            int tp = tags[b * kL + p];
            int tn = tags[b * kL + p + 1];
            s += tr[tn * kT + tp] + g_feats[((size_t)(p + 1) * kB + b) * kT + tn];
        }
        s += __shfl_xor_sync(0xffffffffu, s, 4);
        s += __shfl_xor_sync(0xffffffffu, s, 2);
        s += __shfl_xor_sync(0xffffffffu, s, 1);
        if (lp == 0) gold_s[b] = s + tr[STOP * kT + tags[b * kL + mb]];
    }
    __syncthreads();
    if (tid == 0) {
        float fs = 0.0f, gs = 0.0f;
        for (int bb = 0; bb < kB; bb++) { fs += fwd_s[bb]; gs += gold_s[bb]; }
        out[0] = (fs - gs) * (1.0f / kB);
    }
}

// ---------------- launch ----------------
extern "C" void kernel_launch(void* const* d_in, const int* in_sizes, int n_in,
                              void* d_out, int out_size) {
    const int*   sentence = (const int*)d_in[0];
    const int*   tags     = (const int*)d_in[1];
    const int*   mask     = (const int*)d_in[2];
    const float* embed    = (const float*)d_in[3];
    const float* Wih_f    = (const float*)d_in[4];
    const float* Whh_f    = (const float*)d_in[5];
    const float* b_f      = (const float*)d_in[6];
    const float* Wih_b    = (const float*)d_in[7];
    const float* Whh_b    = (const float*)d_in[8];
    const float* b_b      = (const float*)d_in[9];
    const float* W_tag    = (const float*)d_in[10];
    const float* b_tag    = (const float*)d_in[11];
    const float* trans    = (const float*)d_in[12];
    const float* h0       = (const float*)d_in[13];
    const float* c0       = (const float*)d_in[14];
    (void)in_sizes; (void)n_in; (void)out_size;

    cudaFuncSetAttribute(k_gemm_mma, cudaFuncAttributeMaxDynamicSharedMemorySize, GEMM_SMEM);

    k_gather<<<kL * kB, 64>>>(sentence, embed);
    k_wconv<<<kN, kEMB>>>(Wih_f, Wih_b);

    dim3 gg(kN / 128, (kL * kB) / 128);   // (8, 128)
    k_gemm_mma<<<gg, 256, GEMM_SMEM>>>(b_f, b_b);

    k_lstm<<<64, 256>>>(Whh_f, Whh_b, h0, c0);

    k_feats<<<(kL * kB) / 8, 256>>>(W_tag, b_tag);

    k_crf<<<1, 512>>>(tags, mask, trans, (float*)d_out);
}

// round 12
// speedup vs baseline: 2.2291x; 1.2219x over previous
#include <cuda_runtime.h>
#include <cuda_bf16.h>
#include <cstdint>

// ---------------- problem constants ----------------
constexpr int kL   = 512;
constexpr int kB   = 32;
constexpr int kEMB = 256;
constexpr int kH   = 128;   // per-direction hidden
constexpr int kG   = 512;   // 4*kH gate rows per direction
constexpr int kN   = 1024;  // both directions' gates
constexpr int kT   = 5;
constexpr int START = 3;
constexpr int STOP  = 4;
constexpr int kNCH = 64;    // CRF chunks (8 steps each)

// ---------------- scratch (device globals; no allocs allowed) ----------------
__device__ __nv_bfloat16 g_xh[kL * kB * kEMB];   // x hi (bf16)
__device__ __nv_bfloat16 g_xl[kL * kB * kEMB];   // x lo (bf16 residual)
__device__ __nv_bfloat16 g_wh[kN * kEMB];        // [Wih_f;Wih_b] (bf16)
__device__ float g_gates[kL * kB * kN];          // (l,b,[fwd|bwd] gates)
__device__ float g_h[2 * kL * kB * kH];          // (dir,l,b,j)
__device__ float g_feats[kL * kB * kT];          // (l,b,tag)
__device__ float g_crfM[kB * kNCH * 32];         // per (b,chunk) 5x5 log-matrix

// ---------------- small helpers ----------------
__device__ __forceinline__ float tanhapx(float x) {
    float y;
    asm("tanh.approx.f32 %0, %1;" : "=f"(y) : "f"(x));
    return y;
}
__device__ __forceinline__ float sigapx(float x) {
    return 0.5f * tanhapx(0.5f * x) + 0.5f;
}
__device__ __forceinline__ uint32_t smem_u32(const void* p) {
    uint32_t a;
    asm("{ .reg .u64 t; cvta.to.shared.u64 t, %1; cvt.u32.u64 %0, t; }" : "=r"(a) : "l"(p));
    return a;
}
__device__ __forceinline__ uint32_t swz128(uint32_t off) {
    return off ^ ((off >> 3) & 0x70);
}
__device__ __forceinline__ void cpasync16(uint32_t dst, const void* src) {
    asm volatile("cp.async.cg.shared.global [%0], [%1], 16;" :: "r"(dst), "l"(src));
}
__device__ __forceinline__ void ldsm4(uint32_t* r, uint32_t addr) {
    asm volatile("ldmatrix.sync.aligned.m8n8.x4.shared.b16 {%0,%1,%2,%3}, [%4];"
                 : "=r"(r[0]), "=r"(r[1]), "=r"(r[2]), "=r"(r[3]) : "r"(addr));
}
__device__ __forceinline__ void mma16816(float* d, const uint32_t* a, uint32_t b0, uint32_t b1) {
    asm volatile("mma.sync.aligned.m16n8k16.row.col.f32.bf16.bf16.f32 "
                 "{%0,%1,%2,%3}, {%4,%5,%6,%7}, {%8,%9}, {%0,%1,%2,%3};"
                 : "+f"(d[0]), "+f"(d[1]), "+f"(d[2]), "+f"(d[3])
                 : "r"(a[0]), "r"(a[1]), "r"(a[2]), "r"(a[3]), "r"(b0), "r"(b1));
}
// bf16x2 pack: first arg -> upper half, second -> lower half
__device__ __forceinline__ uint32_t bfpack(float hi, float lo) {
    uint32_t d;
    asm("cvt.rn.bf16x2.f32 %0, %1, %2;" : "=r"(d) : "f"(hi), "f"(lo));
    return d;
}
__device__ __forceinline__ uint32_t hfma2bf(uint32_t a, uint32_t b, uint32_t c) {
    uint32_t d;
    asm("fma.rn.bf16x2 %0, %1, %2, %3;" : "=r"(d) : "r"(a), "r"(b), "r"(c));
    return d;
}
__device__ __forceinline__ float bflo(uint32_t v) { return __uint_as_float(v << 16); }
__device__ __forceinline__ float bfhi(uint32_t v) { return __uint_as_float(v & 0xffff0000u); }

// ---------------- K1: embedding gather + bf16 hi/lo split ----------------
__global__ __launch_bounds__(256) void k_gather(const int* __restrict__ sent,
                                                const float* __restrict__ embed) {
    int lb = blockIdx.x * 4 + (threadIdx.x >> 6);   // l*32 + b
    int tt = threadIdx.x & 63;
    int l = lb >> 5, b = lb & 31;
    int tok = sent[b * kL + l];
    float4 v = ((const float4*)(embed + (size_t)tok * kEMB))[tt];
    float xs[4] = {v.x, v.y, v.z, v.w};
    ushort4 hp, lp;
    unsigned short* hpp = (unsigned short*)&hp;
    unsigned short* lpp = (unsigned short*)&lp;
#pragma unroll
    for (int i = 0; i < 4; i++) {
        __nv_bfloat16 h = __float2bfloat16_rn(xs[i]);
        __nv_bfloat16 lo = __float2bfloat16_rn(xs[i] - __bfloat162float(h));
        hpp[i] = *(unsigned short*)&h;
        lpp[i] = *(unsigned short*)&lo;
    }
    size_t o = (size_t)lb * kEMB + tt * 4;
    *(ushort4*)(g_xh + o) = hp;
    *(ushort4*)(g_xl + o) = lp;
}

// ---------------- K1b: weight bf16 conversion ----------------
__global__ void k_wconv(const float* __restrict__ Wf, const float* __restrict__ Wb) {
    int row = blockIdx.x;             // 0..1023
    int k = threadIdx.x;              // 0..255
    float v = (row < kG) ? Wf[(size_t)row * kEMB + k] : Wb[(size_t)(row - kG) * kEMB + k];
    g_wh[(size_t)row * kEMB + k] = __float2bfloat16_rn(v);
}

// ---------------- K2: mma.sync bf16 GEMM  g_gates = x @ W^T + bias ----------------
// Effective K = 512 = 2 segments of 256: (xh,wh), (xl,wh).
constexpr int GKC = 64;                 // K per chunk (bf16)
constexpr int NCHUNK = 8;               // 512 / 64
constexpr int GBUF = 32768;             // A(16KB)+B(16KB) per buffer
constexpr int GEMM_SMEM = 2 * GBUF;     // 64 KB

__device__ __forceinline__ void ld_chunk(uint32_t sbase, int ck, int buf, int m0, int n0) {
    const int tid = threadIdx.x;
    const int seg = ck >> 2;
    const int koff = (ck & 3) * GKC;
    const __nv_bfloat16* Ag = (seg == 0) ? g_xh : g_xl;
    const __nv_bfloat16* Bg = g_wh;
    const uint32_t abase = sbase + buf * GBUF;
    const uint32_t bbase = abase + 16384;
#pragma unroll
    for (int i = 0; i < 4; i++) {
        int idx = i * 256 + tid;        // 0..1023 : 128 rows x 8 16B-chunks
        int r = idx >> 3;
        int c8 = idx & 7;               // 16B chunk within 128B row
        uint32_t so = swz128((uint32_t)(r * 128 + c8 * 16));
        cpasync16(abase + so, Ag + (size_t)(m0 + r) * kEMB + koff + c8 * 8);
        cpasync16(bbase + so, Bg + (size_t)(n0 + r) * kEMB + koff + c8 * 8);
    }
}

__global__ __launch_bounds__(256, 2) void k_gemm_mma(const float* __restrict__ biasf,
                                                     const float* __restrict__ biasb) {
    extern __shared__ __align__(1024) char smem[];
    const uint32_t sbase = smem_u32(smem);
    const int tid = threadIdx.x;
    const int wid = tid >> 5;
    const int lane = tid & 31;
    const int m0 = blockIdx.y * 128;
    const int n0 = blockIdx.x * 128;
    const int wm = (wid & 1) * 64;      // warp M offset in tile
    const int wn = (wid >> 1) * 32;     // warp N offset in tile

    float acc[4][4][4];
#pragma unroll
    for (int a = 0; a < 4; a++)
#pragma unroll
        for (int b = 0; b < 4; b++)
#pragma unroll
            for (int c = 0; c < 4; c++) acc[a][b][c] = 0.0f;

    ld_chunk(sbase, 0, 0, m0, n0);
    asm volatile("cp.async.commit_group;");

    const int rbase = (lane & 7) + ((lane >> 3) & 1) * 8;
    const int cext = (lane >> 4) * 16;

    for (int ck = 0; ck < NCHUNK; ck++) {
        if (ck + 1 < NCHUNK) ld_chunk(sbase, ck + 1, (ck + 1) & 1, m0, n0);
        asm volatile("cp.async.commit_group;");
        asm volatile("cp.async.wait_group 1;");
        __syncthreads();

        const uint32_t abuf = sbase + (ck & 1) * GBUF;
        const uint32_t bbuf = abuf + 16384;
#pragma unroll
        for (int k16 = 0; k16 < 4; k16++) {
            const int cb = k16 * 32 + cext;
            uint32_t a[4][4];
#pragma unroll
            for (int mi = 0; mi < 4; mi++)
                ldsm4(a[mi], abuf + swz128((uint32_t)((wm + mi * 16 + rbase) * 128 + cb)));
            uint32_t bfr[2][4];
#pragma unroll
            for (int p = 0; p < 2; p++)
                ldsm4(bfr[p], bbuf + swz128((uint32_t)((wn + p * 16 + rbase) * 128 + cb)));
#pragma unroll
            for (int mi = 0; mi < 4; mi++)
#pragma unroll
                for (int nj = 0; nj < 4; nj++)
                    mma16816(acc[mi][nj], a[mi], bfr[nj >> 1][nj & 1], bfr[nj >> 1][(nj & 1) + 2]);
        }
        __syncthreads();
    }

    // epilogue + bias
#pragma unroll
    for (int mi = 0; mi < 4; mi++) {
        int row = m0 + wm + mi * 16 + (lane >> 2);
#pragma unroll
        for (int nj = 0; nj < 4; nj++) {
            int col = n0 + wn + nj * 8 + (lane & 3) * 2;
            float bx = (col < kG) ? biasf[col] : biasb[col - kG];
            float by = (col + 1 < kG) ? biasf[col + 1] : biasb[col + 1 - kG];
            float2 v0 = make_float2(acc[mi][nj][0] + bx, acc[mi][nj][1] + by);
            float2 v1 = make_float2(acc[mi][nj][2] + bx, acc[mi][nj][3] + by);
            *(float2*)(g_gates + (size_t)row * kN + col) = v0;
            *(float2*)(g_gates + (size_t)(row + 8) * kN + col) = v1;
        }
    }
}

// ---------------- K3: LSTM recurrence (256 thr, 2 gate rows/thread) ----------------
__global__ __launch_bounds__(256, 1) void k_lstm(const float* __restrict__ Whh_f,
                                                 const float* __restrict__ Whh_b,
                                                 const float* __restrict__ h0,
                                                 const float* __restrict__ c0) {
    __shared__ float g_s[512];
    __shared__ __align__(16) uint32_t h_bf[64];

    const int t   = threadIdx.x;        // 0..255
    const int blk = blockIdx.x;
    const int dir = blk >> 5;
    const int b   = blk & 31;
    const float* Whh = dir ? Whh_b : Whh_f;
    const int r0 = t;
    const int r1 = t + 256;

    uint32_t w0[64], w1[64];
#pragma unroll
    for (int i = 0; i < 64; i++) {
        float2 a = *(const float2*)(Whh + (size_t)r0 * kH + 2 * i);
        float2 d = *(const float2*)(Whh + (size_t)r1 * kH + 2 * i);
        w0[i] = bfpack(a.y, a.x);
        w1[i] = bfpack(d.y, d.x);
    }

    float c = 0.0f;
    if (t < kH) {
        c = c0[(dir * kB + b) * kH + t];
        float hini = h0[(dir * kB + b) * kH + t];
        float hn = __shfl_down_sync(0xffffffffu, hini, 1);
        if (!(t & 1)) h_bf[t >> 1] = bfpack(hn, hini);
    }
    __syncthreads();

    int l = dir ? (kL - 1) : 0;
    const int step = dir ? -1 : 1;
    const int gofs = dir ? kG : 0;

    float pre0 = g_gates[((size_t)l * kB + b) * kN + gofs + r0];
    float pre1 = g_gates[((size_t)l * kB + b) * kN + gofs + r1];

    for (int s = 0; s < kL; s++) {
        int ln = l + step;
        int lnc = min(max(ln, 0), kL - 1);
        const float* gnext = g_gates + ((size_t)lnc * kB + b) * kN + gofs;
        float pn0 = gnext[r0];
        float pn1 = gnext[r1];

        uint32_t a0 = 0u, a1 = 0u, a2 = 0u, a3 = 0u;
        uint32_t d0 = 0u, d1 = 0u, d2 = 0u, d3 = 0u;
        const uint4* hb = (const uint4*)h_bf;
#pragma unroll
        for (int i = 0; i < 16; i++) {
            uint4 hv = hb[i];
            a0 = hfma2bf(w0[4 * i + 0], hv.x, a0);
            a1 = hfma2bf(w0[4 * i + 1], hv.y, a1);
            a2 = hfma2bf(w0[4 * i + 2], hv.z, a2);
            a3 = hfma2bf(w0[4 * i + 3], hv.w, a3);
            d0 = hfma2bf(w1[4 * i + 0], hv.x, d0);
            d1 = hfma2bf(w1[4 * i + 1], hv.y, d1);
            d2 = hfma2bf(w1[4 * i + 2], hv.z, d2);
            d3 = hfma2bf(w1[4 * i + 3], hv.w, d3);
        }
        g_s[r0] = pre0 + ((bflo(a0) + bfhi(a0)) + (bflo(a1) + bfhi(a1)))
                       + ((bflo(a2) + bfhi(a2)) + (bflo(a3) + bfhi(a3)));
        g_s[r1] = pre1 + ((bflo(d0) + bfhi(d0)) + (bflo(d1) + bfhi(d1)))
                       + ((bflo(d2) + bfhi(d2)) + (bflo(d3) + bfhi(d3)));
        __syncthreads();

        if (t < kH) {
            float gi = g_s[t];
            float gf = g_s[kH + t];
            float gg = g_s[2 * kH + t];
            float go = g_s[3 * kH + t];
            c = sigapx(gf) * c + sigapx(gi) * tanhapx(gg);
            float h = sigapx(go) * tanhapx(c);
            float hn = __shfl_down_sync(0xffffffffu, h, 1);
            if (!(t & 1)) h_bf[t >> 1] = bfpack(hn, h);
            g_h[(((size_t)dir * kL + l) * kB + b) * kH + t] = h;
        }
        __syncthreads();

        pre0 = pn0;
        pre1 = pn1;
        l = ln;
    }
}

// ---------------- K4: feats = concat(hf,hb) @ W_tag^T + b_tag ----------------
__global__ void k_feats(const float* __restrict__ Wt, const float* __restrict__ bt) {
    int lb = blockIdx.x * 8 + (threadIdx.x >> 5);
    int lane = threadIdx.x & 31;
    const float4* hbase = (const float4*)g_h;
    float4 a = hbase[(size_t)lb * 32 + lane];
    float4 cc = hbase[(size_t)kL * kB * 32 + (size_t)lb * 32 + lane];
#pragma unroll
    for (int tag = 0; tag < kT; tag++) {
        float4 w0 = *(const float4*)(Wt + tag * 2 * kH + lane * 4);
        float4 w1 = *(const float4*)(Wt + tag * 2 * kH + kH + lane * 4);
        float p = a.x * w0.x + a.y * w0.y + a.z * w0.z + a.w * w0.w
                + cc.x * w1.x + cc.y * w1.y + cc.z * w1.z + cc.w * w1.w;
        p += __shfl_xor_sync(0xffffffffu, p, 16);
        p += __shfl_xor_sync(0xffffffffu, p, 8);
        p += __shfl_xor_sync(0xffffffffu, p, 4);
        p += __shfl_xor_sync(0xffffffffu, p, 2);
        p += __shfl_xor_sync(0xffffffffu, p, 1);
        if (lane == 0) g_feats[(size_t)lb * kT + tag] = p + bt[tag];
    }
}

// ---------------- K5a: CRF chunk matrices ----------------
// 2048 warps: (b, chunk k). Chunk k composes A_l for l = 1+8k .. min(8k+8, 510)
// where A_l(i,j) = feat_l(i) + tr(i,j). Lane i*5+j holds M(i,j).
// Loop bounds are warp-uniform (same b,k across the warp) -> full-mask shfl OK.
__global__ __launch_bounds__(256) void k_crf_chunks(const float* __restrict__ tr) {
    int gw = blockIdx.x * 8 + (threadIdx.x >> 5);
    int lane = threadIdx.x & 31;
    int b = gw >> 6;
    int k = gw & (kNCH - 1);
    int i = lane / 5; if (i > 4) i = 4;
    int j = lane - (lane / 5) * 5; if (j > 4) j = 4;
    int l0 = 1 + 8 * k;
    int lend = min(l0 + 7, kL - 2);

    float tri[5];
#pragma unroll
    for (int jj = 0; jj < 5; jj++) tri[jj] = tr[i * kT + jj];

    float M = g_feats[((size_t)l0 * kB + b) * kT + i] + tri[j];
    for (int l = l0 + 1; l <= lend; l++) {
        float fi = g_feats[((size_t)l * kB + b) * kT + i];
        float m0 = __shfl_sync(0xffffffffu, M, 0 + j);
        float m1 = __shfl_sync(0xffffffffu, M, 5 + j);
        float m2 = __shfl_sync(0xffffffffu, M, 10 + j);
        float m3 = __shfl_sync(0xffffffffu, M, 15 + j);
        float m4 = __shfl_sync(0xffffffffu, M, 20 + j);
        float t0 = fi + tri[0] + m0, t1 = fi + tri[1] + m1, t2 = fi + tri[2] + m2;
        float t3 = fi + tri[3] + m3, t4 = fi + tri[4] + m4;
        float mx = fmaxf(fmaxf(fmaxf(t0, t1), fmaxf(t2, t3)), t4);
        float ss = __expf(t0 - mx) + __expf(t1 - mx) + __expf(t2 - mx)
                 + __expf(t3 - mx) + __expf(t4 - mx);
        M = mx + __logf(ss);
    }
    if (lane < 25) g_crfM[((size_t)(b * kNCH + k)) * 32 + lane] = M;
}

// ---------------- K5b: CRF apply + gold score ----------------
// Per-subgroup (8 lanes, one batch) loop trip counts differ WITHIN a warp,
// so every shfl inside those loops uses the subgroup mask (0xFF << base).
__global__ __launch_bounds__(512) void k_crf(const int* __restrict__ tags,
                                             const int* __restrict__ mask,
                                             const float* __restrict__ tr,
                                             float* __restrict__ out) {
    __shared__ float fwd_s[kB];
    __shared__ float gold_s[kB];
    const int tid = threadIdx.x;
    const int w = tid >> 5, lane = tid & 31;

    if (w < 8) {
        const int bi = lane >> 3;
        const int i  = lane & 7;
        const int b  = w * 4 + bi;
        const int ie = (i < kT) ? i : (kT - 1);
        const int base = lane & 24;
        const uint32_t gmask = 0xFFu << base;   // subgroup mask

        float tr0 = tr[ie * kT + 0], tr1 = tr[ie * kT + 1], tr2 = tr[ie * kT + 2];
        float tr3 = tr[ie * kT + 3], tr4 = tr[ie * kT + 4];
        float alpha = (i == START) ? 0.0f : -10000.0f;
        const int mb = mask[b];
        const int K = mb >> 3;          // full chunks (each covers 8 steps)

        // ---- fold through precomputed chunk matrices ----
        const float* Cb = g_crfM + (size_t)b * kNCH * 32;
        float cc[5] = {0.f, 0.f, 0.f, 0.f, 0.f};
        if (K > 0) {
#pragma unroll
            for (int jj = 0; jj < 5; jj++) cc[jj] = Cb[ie * 5 + jj];
        }
        for (int k = 0; k < K; k++) {
            float cn[5] = {0.f, 0.f, 0.f, 0.f, 0.f};
            if (k + 1 < K) {
#pragma unroll
                for (int jj = 0; jj < 5; jj++) cn[jj] = Cb[(k + 1) * 32 + ie * 5 + jj];
            }
            float a0 = __shfl_sync(gmask, alpha, base + 0);
            float a1 = __shfl_sync(gmask, alpha, base + 1);
            float a2 = __shfl_sync(gmask, alpha, base + 2);
            float a3 = __shfl_sync(gmask, alpha, base + 3);
            float a4 = __shfl_sync(gmask, alpha, base + 4);
            float t0 = cc[0] + a0, t1 = cc[1] + a1, t2 = cc[2] + a2;
            float t3 = cc[3] + a3, t4 = cc[4] + a4;
            float m = fmaxf(fmaxf(fmaxf(t0, t1), fmaxf(t2, t3)), t4);
            float ss = __expf(t0 - m) + __expf(t1 - m) + __expf(t2 - m)
                     + __expf(t3 - m) + __expf(t4 - m);
            alpha = m + __logf(ss);
#pragma unroll
            for (int jj = 0; jj < 5; jj++) cc[jj] = cn[jj];
        }
        // ---- scalar tail: l = 8K+1 .. mb ----
        for (int l = 8 * K + 1; l <= mb; l++) {
            float f = g_feats[((size_t)l * kB + b) * kT + ie];
            float a0 = __shfl_sync(gmask, alpha, base + 0);
            float a1 = __shfl_sync(gmask, alpha, base + 1);
            float a2 = __shfl_sync(gmask, alpha, base + 2);
            float a3 = __shfl_sync(gmask, alpha, base + 3);
            float a4 = __shfl_sync(gmask, alpha, base + 4);
            float v0 = a0 + tr0, v1 = a1 + tr1, v2 = a2 + tr2;
            float v3 = a3 + tr3, v4 = a4 + tr4;
            float m = fmaxf(fmaxf(fmaxf(v0, v1), fmaxf(v2, v3)), v4);
            float ss = __expf(v0 - m) + __expf(v1 - m) + __expf(v2 - m)
                     + __expf(v3 - m) + __expf(v4 - m);
            alpha = f + m + __logf(ss);
        }
        // ---- terminal logsumexp with trans[STOP] ----
        float t0 = __shfl_sync(gmask, alpha, base + 0) + tr[STOP * kT + 0];
        float t1 = __shfl_sync(gmask, alpha, base + 1) + tr[STOP * kT + 1];
        float t2 = __shfl_sync(gmask, alpha, base + 2) + tr[STOP * kT + 2];
        float t3 = __shfl_sync(gmask, alpha, base + 3) + tr[STOP * kT + 3];
        float t4 = __shfl_sync(gmask, alpha, base + 4) + tr[STOP * kT + 4];
        float m = fmaxf(fmaxf(fmaxf(t0, t1), fmaxf(t2, t3)), t4);
        float ss = __expf(t0 - m) + __expf(t1 - m) + __expf(t2 - m)
                 + __expf(t3 - m) + __expf(t4 - m);
        if (i == 0) fwd_s[b] = m + __logf(ss);
    } else if (w < 16) {
        const int b = (w - 8) * 4 + (lane >> 3);
        const int lp = lane & 7;
        const int base = lane & 24;
        const uint32_t gmask = 0xFFu << base;
        const int mb = mask[b];
        float s = 0.0f;
        for (int p = lp; p < mb; p += 8) {
            int tp = tags[b * kL + p];
            int tn = tags[b * kL + p + 1];
            s += tr[tn * kT + tp] + g_feats[((size_t)(p + 1) * kB + b) * kT + tn];
        }
        s += __shfl_xor_sync(gmask, s, 4);
        s += __shfl_xor_sync(gmask, s, 2);
        s += __shfl_xor_sync(gmask, s, 1);
        if (lp == 0) gold_s[b] = s + tr[STOP * kT + tags[b * kL + mb]];
    }
    __syncthreads();
    if (tid == 0) {
        float fs = 0.0f, gs = 0.0f;
        for (int bb = 0; bb < kB; bb++) { fs += fwd_s[bb]; gs += gold_s[bb]; }
        out[0] = (fs - gs) * (1.0f / kB);
    }
}

// ---------------- launch ----------------
extern "C" void kernel_launch(void* const* d_in, const int* in_sizes, int n_in,
                              void* d_out, int out_size) {
    const int*   sentence = (const int*)d_in[0];
    const int*   tags     = (const int*)d_in[1];
    const int*   mask     = (const int*)d_in[2];
    const float* embed    = (const float*)d_in[3];
    const float* Wih_f    = (const float*)d_in[4];
    const float* Whh_f    = (const float*)d_in[5];
    const float* b_f      = (const float*)d_in[6];
    const float* Wih_b    = (const float*)d_in[7];
    const float* Whh_b    = (const float*)d_in[8];
    const float* b_b      = (const float*)d_in[9];
    const float* W_tag    = (const float*)d_in[10];
    const float* b_tag    = (const float*)d_in[11];
    const float* trans    = (const float*)d_in[12];
    const float* h0       = (const float*)d_in[13];
    const float* c0       = (const float*)d_in[14];
    (void)in_sizes; (void)n_in; (void)out_size;

    cudaFuncSetAttribute(k_gemm_mma, cudaFuncAttributeMaxDynamicSharedMemorySize, GEMM_SMEM);

    k_gather<<<(kL * kB) / 4, 256>>>(sentence, embed);
    k_wconv<<<kN, kEMB>>>(Wih_f, Wih_b);

    dim3 gg(kN / 128, (kL * kB) / 128);   // (8, 128)
    k_gemm_mma<<<gg, 256, GEMM_SMEM>>>(b_f, b_b);

    k_lstm<<<64, 256>>>(Whh_f, Whh_b, h0, c0);

    k_feats<<<(kL * kB) / 8, 256>>>(W_tag, b_tag);

    k_crf_chunks<<<(kB * kNCH) / 8, 256>>>(trans);

    k_crf<<<1, 512>>>(tags, mask, trans, (float*)d_out);
}

// round 13
// speedup vs baseline: 2.4189x; 1.0851x over previous
#include <cuda_runtime.h>
#include <cuda_bf16.h>
#include <cstdint>

// ---------------- problem constants ----------------
constexpr int kL   = 512;
constexpr int kB   = 32;
constexpr int kEMB = 256;
constexpr int kH   = 128;   // per-direction hidden
constexpr int kG   = 512;   // 4*kH gate rows per direction
constexpr int kN   = 1024;  // both directions' gates
constexpr int kT   = 5;
constexpr int START = 3;
constexpr int STOP  = 4;
constexpr int kNCH = 64;    // CRF chunks (8 steps each)

// ---------------- scratch (device globals; no allocs allowed) ----------------
__device__ __nv_bfloat16 g_xh[kL * kB * kEMB];   // x (bf16)
__device__ __nv_bfloat16 g_wh[kN * kEMB];        // [Wih_f;Wih_b] (bf16)
__device__ float g_gates[kL * kB * kN];          // (l,b,[fwd|bwd] gates)
__device__ float g_h[2 * kL * kB * kH];          // (dir,l,b,j)
__device__ float g_feats[kL * kB * kT];          // (l,b,tag)
__device__ float g_crfM[kB * kNCH * 32];         // per (b,chunk) 5x5 log-matrix

// ---------------- small helpers ----------------
__device__ __forceinline__ float tanhapx(float x) {
    float y;
    asm("tanh.approx.f32 %0, %1;" : "=f"(y) : "f"(x));
    return y;
}
__device__ __forceinline__ float sigapx(float x) {
    return 0.5f * tanhapx(0.5f * x) + 0.5f;
}
__device__ __forceinline__ uint32_t smem_u32(const void* p) {
    uint32_t a;
    asm("{ .reg .u64 t; cvta.to.shared.u64 t, %1; cvt.u32.u64 %0, t; }" : "=r"(a) : "l"(p));
    return a;
}
__device__ __forceinline__ uint32_t swz128(uint32_t off) {
    return off ^ ((off >> 3) & 0x70);
}
__device__ __forceinline__ void cpasync16(uint32_t dst, const void* src) {
    asm volatile("cp.async.cg.shared.global [%0], [%1], 16;" :: "r"(dst), "l"(src));
}
__device__ __forceinline__ void ldsm4(uint32_t* r, uint32_t addr) {
    asm volatile("ldmatrix.sync.aligned.m8n8.x4.shared.b16 {%0,%1,%2,%3}, [%4];"
                 : "=r"(r[0]), "=r"(r[1]), "=r"(r[2]), "=r"(r[3]) : "r"(addr));
}
__device__ __forceinline__ void mma16816(float* d, const uint32_t* a, uint32_t b0, uint32_t b1) {
    asm volatile("mma.sync.aligned.m16n8k16.row.col.f32.bf16.bf16.f32 "
                 "{%0,%1,%2,%3}, {%4,%5,%6,%7}, {%8,%9}, {%0,%1,%2,%3};"
                 : "+f"(d[0]), "+f"(d[1]), "+f"(d[2]), "+f"(d[3])
                 : "r"(a[0]), "r"(a[1]), "r"(a[2]), "r"(a[3]), "r"(b0), "r"(b1));
}
// bf16x2 pack: first arg -> upper half, second -> lower half
__device__ __forceinline__ uint32_t bfpack(float hi, float lo) {
    uint32_t d;
    asm("cvt.rn.bf16x2.f32 %0, %1, %2;" : "=r"(d) : "f"(hi), "f"(lo));
    return d;
}
__device__ __forceinline__ uint32_t hfma2bf(uint32_t a, uint32_t b, uint32_t c) {
    uint32_t d;
    asm("fma.rn.bf16x2 %0, %1, %2, %3;" : "=r"(d) : "r"(a), "r"(b), "r"(c));
    return d;
}
__device__ __forceinline__ float bflo(uint32_t v) { return __uint_as_float(v << 16); }
__device__ __forceinline__ float bfhi(uint32_t v) { return __uint_as_float(v & 0xffff0000u); }

// ---------------- K1: embedding gather (bf16) ----------------
__global__ __launch_bounds__(256) void k_gather(const int* __restrict__ sent,
                                                const float* __restrict__ embed) {
    int lb = blockIdx.x * 4 + (threadIdx.x >> 6);   // l*32 + b
    int tt = threadIdx.x & 63;
    int l = lb >> 5, b = lb & 31;
    int tok = sent[b * kL + l];
    float4 v = ((const float4*)(embed + (size_t)tok * kEMB))[tt];
    ushort4 hp;
    unsigned short* hpp = (unsigned short*)&hp;
    float xs[4] = {v.x, v.y, v.z, v.w};
#pragma unroll
    for (int i = 0; i < 4; i++) {
        __nv_bfloat16 h = __float2bfloat16_rn(xs[i]);
        hpp[i] = *(unsigned short*)&h;
    }
    *(ushort4*)(g_xh + (size_t)lb * kEMB + tt * 4) = hp;
}

// ---------------- K1b: weight bf16 conversion ----------------
__global__ void k_wconv(const float* __restrict__ Wf, const float* __restrict__ Wb) {
    int row = blockIdx.x;             // 0..1023
    int k = threadIdx.x;              // 0..255
    float v = (row < kG) ? Wf[(size_t)row * kEMB + k] : Wb[(size_t)(row - kG) * kEMB + k];
    g_wh[(size_t)row * kEMB + k] = __float2bfloat16_rn(v);
}

// ---------------- K2: mma.sync bf16 GEMM  g_gates = x @ W^T + bias ----------------
// K = 256 (pure bf16 operands).
constexpr int GKC = 64;                 // K per chunk (bf16)
constexpr int NCHUNK = 4;               // 256 / 64
constexpr int GBUF = 32768;             // A(16KB)+B(16KB) per buffer
constexpr int GEMM_SMEM = 2 * GBUF;     // 64 KB

__device__ __forceinline__ void ld_chunk(uint32_t sbase, int ck, int buf, int m0, int n0) {
    const int tid = threadIdx.x;
    const int koff = ck * GKC;
    const uint32_t abase = sbase + buf * GBUF;
    const uint32_t bbase = abase + 16384;
#pragma unroll
    for (int i = 0; i < 4; i++) {
        int idx = i * 256 + tid;        // 0..1023 : 128 rows x 8 16B-chunks
        int r = idx >> 3;
        int c8 = idx & 7;               // 16B chunk within 128B row
        uint32_t so = swz128((uint32_t)(r * 128 + c8 * 16));
        cpasync16(abase + so, g_xh + (size_t)(m0 + r) * kEMB + koff + c8 * 8);
        cpasync16(bbase + so, g_wh + (size_t)(n0 + r) * kEMB + koff + c8 * 8);
    }
}

__global__ __launch_bounds__(256, 2) void k_gemm_mma(const float* __restrict__ biasf,
                                                     const float* __restrict__ biasb) {
    extern __shared__ __align__(1024) char smem[];
    const uint32_t sbase = smem_u32(smem);
    const int tid = threadIdx.x;
    const int wid = tid >> 5;
    const int lane = tid & 31;
    const int m0 = blockIdx.y * 128;
    const int n0 = blockIdx.x * 128;
    const int wm = (wid & 1) * 64;      // warp M offset in tile
    const int wn = (wid >> 1) * 32;     // warp N offset in tile

    float acc[4][4][4];
#pragma unroll
    for (int a = 0; a < 4; a++)
#pragma unroll
        for (int b = 0; b < 4; b++)
#pragma unroll
            for (int c = 0; c < 4; c++) acc[a][b][c] = 0.0f;

    ld_chunk(sbase, 0, 0, m0, n0);
    asm volatile("cp.async.commit_group;");

    const int rbase = (lane & 7) + ((lane >> 3) & 1) * 8;
    const int cext = (lane >> 4) * 16;

    for (int ck = 0; ck < NCHUNK; ck++) {
        if (ck + 1 < NCHUNK) ld_chunk(sbase, ck + 1, (ck + 1) & 1, m0, n0);
        asm volatile("cp.async.commit_group;");
        asm volatile("cp.async.wait_group 1;");
        __syncthreads();

        const uint32_t abuf = sbase + (ck & 1) * GBUF;
        const uint32_t bbuf = abuf + 16384;
#pragma unroll
        for (int k16 = 0; k16 < 4; k16++) {
            const int cb = k16 * 32 + cext;
            uint32_t a[4][4];
#pragma unroll
            for (int mi = 0; mi < 4; mi++)
                ldsm4(a[mi], abuf + swz128((uint32_t)((wm + mi * 16 + rbase) * 128 + cb)));
            uint32_t bfr[2][4];
#pragma unroll
            for (int p = 0; p < 2; p++)
                ldsm4(bfr[p], bbuf + swz128((uint32_t)((wn + p * 16 + rbase) * 128 + cb)));
#pragma unroll
            for (int mi = 0; mi < 4; mi++)
#pragma unroll
                for (int nj = 0; nj < 4; nj++)
                    mma16816(acc[mi][nj], a[mi], bfr[nj >> 1][nj & 1], bfr[nj >> 1][(nj & 1) + 2]);
        }
        __syncthreads();
    }

    // epilogue + bias
#pragma unroll
    for (int mi = 0; mi < 4; mi++) {
        int row = m0 + wm + mi * 16 + (lane >> 2);
#pragma unroll
        for (int nj = 0; nj < 4; nj++) {
            int col = n0 + wn + nj * 8 + (lane & 3) * 2;
            float bx = (col < kG) ? biasf[col] : biasb[col - kG];
            float by = (col + 1 < kG) ? biasf[col + 1] : biasb[col + 1 - kG];
            float2 v0 = make_float2(acc[mi][nj][0] + bx, acc[mi][nj][1] + by);
            float2 v1 = make_float2(acc[mi][nj][2] + bx, acc[mi][nj][3] + by);
            *(float2*)(g_gates + (size_t)row * kN + col) = v0;
            *(float2*)(g_gates + (size_t)(row + 8) * kN + col) = v1;
        }
    }
}

// ---------------- K3: LSTM recurrence (256 thr, 2 gate rows/thread) ----------------
__global__ __launch_bounds__(256, 1) void k_lstm(const float* __restrict__ Whh_f,
                                                 const float* __restrict__ Whh_b,
                                                 const float* __restrict__ h0,
                                                 const float* __restrict__ c0) {
    __shared__ float g_s[512];
    __shared__ __align__(16) uint32_t h_bf[64];

    const int t   = threadIdx.x;        // 0..255
    const int blk = blockIdx.x;
    const int dir = blk >> 5;
    const int b   = blk & 31;
    const float* Whh = dir ? Whh_b : Whh_f;
    const int r0 = t;
    const int r1 = t + 256;

    uint32_t w0[64], w1[64];
#pragma unroll
    for (int i = 0; i < 64; i++) {
        float2 a = *(const float2*)(Whh + (size_t)r0 * kH + 2 * i);
        float2 d = *(const float2*)(Whh + (size_t)r1 * kH + 2 * i);
        w0[i] = bfpack(a.y, a.x);
        w1[i] = bfpack(d.y, d.x);
    }

    float c = 0.0f;
    if (t < kH) {
        c = c0[(dir * kB + b) * kH + t];
        float hini = h0[(dir * kB + b) * kH + t];
        float hn = __shfl_down_sync(0xffffffffu, hini, 1);
        if (!(t & 1)) h_bf[t >> 1] = bfpack(hn, hini);
    }
    __syncthreads();

    int l = dir ? (kL - 1) : 0;
    const int step = dir ? -1 : 1;
    const int gofs = dir ? kG : 0;

    float pre0 = g_gates[((size_t)l * kB + b) * kN + gofs + r0];
    float pre1 = g_gates[((size_t)l * kB + b) * kN + gofs + r1];

    for (int s = 0; s < kL; s++) {
        int ln = l + step;
        int lnc = min(max(ln, 0), kL - 1);
        const float* gnext = g_gates + ((size_t)lnc * kB + b) * kN + gofs;
        float pn0 = gnext[r0];
        float pn1 = gnext[r1];

        uint32_t a0 = 0u, a1 = 0u, a2 = 0u, a3 = 0u;
        uint32_t d0 = 0u, d1 = 0u, d2 = 0u, d3 = 0u;
        const uint4* hb = (const uint4*)h_bf;
#pragma unroll
        for (int i = 0; i < 16; i++) {
            uint4 hv = hb[i];
            a0 = hfma2bf(w0[4 * i + 0], hv.x, a0);
            a1 = hfma2bf(w0[4 * i + 1], hv.y, a1);
            a2 = hfma2bf(w0[4 * i + 2], hv.z, a2);
            a3 = hfma2bf(w0[4 * i + 3], hv.w, a3);
            d0 = hfma2bf(w1[4 * i + 0], hv.x, d0);
            d1 = hfma2bf(w1[4 * i + 1], hv.y, d1);
            d2 = hfma2bf(w1[4 * i + 2], hv.z, d2);
            d3 = hfma2bf(w1[4 * i + 3], hv.w, d3);
        }
        g_s[r0] = pre0 + ((bflo(a0) + bfhi(a0)) + (bflo(a1) + bfhi(a1)))
                       + ((bflo(a2) + bfhi(a2)) + (bflo(a3) + bfhi(a3)));
        g_s[r1] = pre1 + ((bflo(d0) + bfhi(d0)) + (bflo(d1) + bfhi(d1)))
                       + ((bflo(d2) + bfhi(d2)) + (bflo(d3) + bfhi(d3)));
        __syncthreads();

        if (t < kH) {
            float gi = g_s[t];
            float gf = g_s[kH + t];
            float gg = g_s[2 * kH + t];
            float go = g_s[3 * kH + t];
            c = sigapx(gf) * c + sigapx(gi) * tanhapx(gg);
            float h = sigapx(go) * tanhapx(c);
            float hn = __shfl_down_sync(0xffffffffu, h, 1);
            if (!(t & 1)) h_bf[t >> 1] = bfpack(hn, h);
            g_h[(((size_t)dir * kL + l) * kB + b) * kH + t] = h;
        }
        __syncthreads();

        pre0 = pn0;
        pre1 = pn1;
        l = ln;
    }
}

// ---------------- K4: feats = concat(hf,hb) @ W_tag^T + b_tag ----------------
__global__ void k_feats(const float* __restrict__ Wt, const float* __restrict__ bt) {
    int lb = blockIdx.x * 8 + (threadIdx.x >> 5);
    int lane = threadIdx.x & 31;
    const float4* hbase = (const float4*)g_h;
    float4 a = hbase[(size_t)lb * 32 + lane];
    float4 cc = hbase[(size_t)kL * kB * 32 + (size_t)lb * 32 + lane];
#pragma unroll
    for (int tag = 0; tag < kT; tag++) {
        float4 w0 = *(const float4*)(Wt + tag * 2 * kH + lane * 4);
        float4 w1 = *(const float4*)(Wt + tag * 2 * kH + kH + lane * 4);
        float p = a.x * w0.x + a.y * w0.y + a.z * w0.z + a.w * w0.w
                + cc.x * w1.x + cc.y * w1.y + cc.z * w1.z + cc.w * w1.w;
        p += __shfl_xor_sync(0xffffffffu, p, 16);
        p += __shfl_xor_sync(0xffffffffu, p, 8);
        p += __shfl_xor_sync(0xffffffffu, p, 4);
        p += __shfl_xor_sync(0xffffffffu, p, 2);
        p += __shfl_xor_sync(0xffffffffu, p, 1);
        if (lane == 0) g_feats[(size_t)lb * kT + tag] = p + bt[tag];
    }
}

// ---------------- K5a: CRF chunk matrices ----------------
// Warp-uniform loop bounds (same b,k across warp) -> full-mask shfl OK.
__global__ __launch_bounds__(256) void k_crf_chunks(const float* __restrict__ tr) {
    int gw = blockIdx.x * 8 + (threadIdx.x >> 5);
    int lane = threadIdx.x & 31;
    int b = gw >> 6;
    int k = gw & (kNCH - 1);
    int i = lane / 5; if (i > 4) i = 4;
    int j = lane - (lane / 5) * 5; if (j > 4) j = 4;
    int l0 = 1 + 8 * k;
    int lend = min(l0 + 7, kL - 2);

    float tri[5];
#pragma unroll
    for (int jj = 0; jj < 5; jj++) tri[jj] = tr[i * kT + jj];

    float M = g_feats[((size_t)l0 * kB + b) * kT + i] + tri[j];
    for (int l = l0 + 1; l <= lend; l++) {
        float fi = g_feats[((size_t)l * kB + b) * kT + i];
        float m0 = __shfl_sync(0xffffffffu, M, 0 + j);
        float m1 = __shfl_sync(0xffffffffu, M, 5 + j);
        float m2 = __shfl_sync(0xffffffffu, M, 10 + j);
        float m3 = __shfl_sync(0xffffffffu, M, 15 + j);
        float m4 = __shfl_sync(0xffffffffu, M, 20 + j);
        float t0 = fi + tri[0] + m0, t1 = fi + tri[1] + m1, t2 = fi + tri[2] + m2;
        float t3 = fi + tri[3] + m3, t4 = fi + tri[4] + m4;
        float mx = fmaxf(fmaxf(fmaxf(t0, t1), fmaxf(t2, t3)), t4);
        float ss = __expf(t0 - mx) + __expf(t1 - mx) + __expf(t2 - mx)
                 + __expf(t3 - mx) + __expf(t4 - mx);
        M = mx + __logf(ss);
    }
    if (lane < 25) g_crfM[((size_t)(b * kNCH + k)) * 32 + lane] = M;
}

// ---------------- K5b: CRF apply + gold score ----------------
// Per-subgroup loop trip counts differ within a warp -> subgroup-mask shfl.
__global__ __launch_bounds__(512) void k_crf(const int* __restrict__ tags,
                                             const int* __restrict__ mask,
                                             const float* __restrict__ tr,
                                             float* __restrict__ out) {
    __shared__ float fwd_s[kB];
    __shared__ float gold_s[kB];
    const int tid = threadIdx.x;
    const int w = tid >> 5, lane = tid & 31;

    if (w < 8) {
        const int bi = lane >> 3;
        const int i  = lane & 7;
        const int b  = w * 4 + bi;
        const int ie = (i < kT) ? i : (kT - 1);
        const int base = lane & 24;
        const uint32_t gmask = 0xFFu << base;   // subgroup mask

        float tr0 = tr[ie * kT + 0], tr1 = tr[ie * kT + 1], tr2 = tr[ie * kT + 2];
        float tr3 = tr[ie * kT + 3], tr4 = tr[ie * kT + 4];
        float alpha = (i == START) ? 0.0f : -10000.0f;
        const int mb = mask[b];
        const int K = mb >> 3;          // full chunks

        const float* Cb = g_crfM + (size_t)b * kNCH * 32;
        float cc[5] = {0.f, 0.f, 0.f, 0.f, 0.f};
        if (K > 0) {
#pragma unroll
            for (int jj = 0; jj < 5; jj++) cc[jj] = Cb[ie * 5 + jj];
        }
        for (int k = 0; k < K; k++) {
            float cn[5] = {0.f, 0.f, 0.f, 0.f, 0.f};
            if (k + 1 < K) {
#pragma unroll
                for (int jj = 0; jj < 5; jj++) cn[jj] = Cb[(k + 1) * 32 + ie * 5 + jj];
            }
            float a0 = __shfl_sync(gmask, alpha, base + 0);
            float a1 = __shfl_sync(gmask, alpha, base + 1);
            float a2 = __shfl_sync(gmask, alpha, base + 2);
            float a3 = __shfl_sync(gmask, alpha, base + 3);
            float a4 = __shfl_sync(gmask, alpha, base + 4);
            float t0 = cc[0] + a0, t1 = cc[1] + a1, t2 = cc[2] + a2;
            float t3 = cc[3] + a3, t4 = cc[4] + a4;
            float m = fmaxf(fmaxf(fmaxf(t0, t1), fmaxf(t2, t3)), t4);
            float ss = __expf(t0 - m) + __expf(t1 - m) + __expf(t2 - m)
                     + __expf(t3 - m) + __expf(t4 - m);
            alpha = m + __logf(ss);
#pragma unroll
            for (int jj = 0; jj < 5; jj++) cc[jj] = cn[jj];
        }
        for (int l = 8 * K + 1; l <= mb; l++) {
            float f = g_feats[((size_t)l * kB + b) * kT + ie];
            float a0 = __shfl_sync(gmask, alpha, base + 0);
            float a1 = __shfl_sync(gmask, alpha, base + 1);
            float a2 = __shfl_sync(gmask, alpha, base + 2);
            float a3 = __shfl_sync(gmask, alpha, base + 3);
            float a4 = __shfl_sync(gmask, alpha, base + 4);
            float v0 = a0 + tr0, v1 = a1 + tr1, v2 = a2 + tr2;
            float v3 = a3 + tr3, v4 = a4 + tr4;
            float m = fmaxf(fmaxf(fmaxf(v0, v1), fmaxf(v2, v3)), v4);
            float ss = __expf(v0 - m) + __expf(v1 - m) + __expf(v2 - m)
                     + __expf(v3 - m) + __expf(v4 - m);
            alpha = f + m + __logf(ss);
        }
        float t0 = __shfl_sync(gmask, alpha, base + 0) + tr[STOP * kT + 0];
        float t1 = __shfl_sync(gmask, alpha, base + 1) + tr[STOP * kT + 1];
        float t2 = __shfl_sync(gmask, alpha, base + 2) + tr[STOP * kT + 2];
        float t3 = __shfl_sync(gmask, alpha, base + 3) + tr[STOP * kT + 3];
        float t4 = __shfl_sync(gmask, alpha, base + 4) + tr[STOP * kT + 4];
        float m = fmaxf(fmaxf(fmaxf(t0, t1), fmaxf(t2, t3)), t4);
        float ss = __expf(t0 - m) + __expf(t1 - m) + __expf(t2 - m)
                 + __expf(t3 - m) + __expf(t4 - m);
        if (i == 0) fwd_s[b] = m + __logf(ss);
    } else if (w < 16) {
        const int b = (w - 8) * 4 + (lane >> 3);
        const int lp = lane & 7;
        const int base = lane & 24;
        const uint32_t gmask = 0xFFu << base;
        const int mb = mask[b];
        float s = 0.0f;
        for (int p = lp; p < mb; p += 8) {
            int tp = tags[b * kL + p];
            int tn = tags[b * kL + p + 1];
            s += tr[tn * kT + tp] + g_feats[((size_t)(p + 1) * kB + b) * kT + tn];
        }
        s += __shfl_xor_sync(gmask, s, 4);
        s += __shfl_xor_sync(gmask, s, 2);
        s += __shfl_xor_sync(gmask, s, 1);
        if (lp == 0) gold_s[b] = s + tr[STOP * kT + tags[b * kL + mb]];
    }
    __syncthreads();
    if (tid == 0) {
        float fs = 0.0f, gs = 0.0f;
        for (int bb = 0; bb < kB; bb++) { fs += fwd_s[bb]; gs += gold_s[bb]; }
        out[0] = (fs - gs) * (1.0f / kB);
    }
}

// ---------------- launch ----------------
extern "C" void kernel_launch(void* const* d_in, const int* in_sizes, int n_in,
                              void* d_out, int out_size) {
    const int*   sentence = (const int*)d_in[0];
    const int*   tags     = (const int*)d_in[1];
    const int*   mask     = (const int*)d_in[2];
    const float* embed    = (const float*)d_in[3];
    const float* Wih_f    = (const float*)d_in[4];
    const float* Whh_f    = (const float*)d_in[5];
    const float* b_f      = (const float*)d_in[6];
    const float* Wih_b    = (const float*)d_in[7];
    const float* Whh_b    = (const float*)d_in[8];
    const float* b_b      = (const float*)d_in[9];
    const float* W_tag    = (const float*)d_in[10];
    const float* b_tag    = (const float*)d_in[11];
    const float* trans    = (const float*)d_in[12];
    const float* h0       = (const float*)d_in[13];
    const float* c0       = (const float*)d_in[14];
    (void)in_sizes; (void)n_in; (void)out_size;

    cudaFuncSetAttribute(k_gemm_mma, cudaFuncAttributeMaxDynamicSharedMemorySize, GEMM_SMEM);

    k_gather<<<(kL * kB) / 4, 256>>>(sentence, embed);
    k_wconv<<<kN, kEMB>>>(Wih_f, Wih_b);

    dim3 gg(kN / 128, (kL * kB) / 128);   // (8, 128)
    k_gemm_mma<<<gg, 256, GEMM_SMEM>>>(b_f, b_b);

    k_lstm<<<64, 256>>>(Whh_f, Whh_b, h0, c0);

    k_feats<<<(kL * kB) / 8, 256>>>(W_tag, b_tag);

    k_crf_chunks<<<(kB * kNCH) / 8, 256>>>(trans);

    k_crf<<<1, 512>>>(tags, mask, trans, (float*)d_out);
}

// round 14
// speedup vs baseline: 2.4786x; 1.0247x over previous
#include <cuda_runtime.h>
#include <cuda_bf16.h>
#include <cstdint>

// ---------------- problem constants ----------------
constexpr int kL   = 512;
constexpr int kB   = 32;
constexpr int kEMB = 256;
constexpr int kH   = 128;   // per-direction hidden
constexpr int kG   = 512;   // 4*kH gate rows per direction
constexpr int kN   = 1024;  // both directions' gates
constexpr int kT   = 5;
constexpr int START = 3;
constexpr int STOP  = 4;
constexpr int kNCH = 64;    // CRF chunks (8 steps each)

// ---------------- scratch (device globals; no allocs allowed) ----------------
__device__ __nv_bfloat16 g_xh[kL * kB * kEMB];   // x (bf16)
__device__ __nv_bfloat16 g_wh[kN * kEMB];        // [Wih_f;Wih_b] (bf16)
__device__ float g_gates[kL * kB * kN];          // (l,b,[fwd|bwd] gates)
__device__ float g_h[2 * kL * kB * kH];          // (dir,l,b,j)
__device__ float g_feats[kL * kB * kT];          // (l,b,tag)
__device__ float g_crfM[kB * kNCH * 32];         // per (b,chunk) 5x5 log-matrix

// ---------------- small helpers ----------------
__device__ __forceinline__ float tanhapx(float x) {
    float y;
    asm("tanh.approx.f32 %0, %1;" : "=f"(y) : "f"(x));
    return y;
}
__device__ __forceinline__ float sigapx(float x) {
    return 0.5f * tanhapx(0.5f * x) + 0.5f;
}
__device__ __forceinline__ uint32_t smem_u32(const void* p) {
    uint32_t a;
    asm("{ .reg .u64 t; cvta.to.shared.u64 t, %1; cvt.u32.u64 %0, t; }" : "=r"(a) : "l"(p));
    return a;
}
__device__ __forceinline__ uint32_t swz128(uint32_t off) {
    return off ^ ((off >> 3) & 0x70);
}
__device__ __forceinline__ void cpasync16(uint32_t dst, const void* src) {
    asm volatile("cp.async.cg.shared.global [%0], [%1], 16;" :: "r"(dst), "l"(src));
}
__device__ __forceinline__ void ldsm4(uint32_t* r, uint32_t addr) {
    asm volatile("ldmatrix.sync.aligned.m8n8.x4.shared.b16 {%0,%1,%2,%3}, [%4];"
                 : "=r"(r[0]), "=r"(r[1]), "=r"(r[2]), "=r"(r[3]) : "r"(addr));
}
__device__ __forceinline__ void mma16816(float* d, const uint32_t* a, uint32_t b0, uint32_t b1) {
    asm volatile("mma.sync.aligned.m16n8k16.row.col.f32.bf16.bf16.f32 "
                 "{%0,%1,%2,%3}, {%4,%5,%6,%7}, {%8,%9}, {%0,%1,%2,%3};"
                 : "+f"(d[0]), "+f"(d[1]), "+f"(d[2]), "+f"(d[3])
                 : "r"(a[0]), "r"(a[1]), "r"(a[2]), "r"(a[3]), "r"(b0), "r"(b1));
}
// bf16x2 pack: first arg -> upper half, second -> lower half
__device__ __forceinline__ uint32_t bfpack(float hi, float lo) {
    uint32_t d;
    asm("cvt.rn.bf16x2.f32 %0, %1, %2;" : "=r"(d) : "f"(hi), "f"(lo));
    return d;
}
__device__ __forceinline__ uint32_t hfma2bf(uint32_t a, uint32_t b, uint32_t c) {
    uint32_t d;
    asm("fma.rn.bf16x2 %0, %1, %2, %3;" : "=r"(d) : "r"(a), "r"(b), "r"(c));
    return d;
}
__device__ __forceinline__ float bflo(uint32_t v) { return __uint_as_float(v << 16); }
__device__ __forceinline__ float bfhi(uint32_t v) { return __uint_as_float(v & 0xffff0000u); }

// ---------------- K1: fused embedding gather (bf16) + weight conversion ----------------
// blocks [0, 4096): gather, 4 (l,b) rows each. blocks [4096, 5120): wconv rows.
__global__ __launch_bounds__(256) void k_prep(const int* __restrict__ sent,
                                              const float* __restrict__ embed,
                                              const float* __restrict__ Wf,
                                              const float* __restrict__ Wb) {
    if (blockIdx.x < 4096) {
        int lb = blockIdx.x * 4 + (threadIdx.x >> 6);   // l*32 + b
        int tt = threadIdx.x & 63;
        int l = lb >> 5, b = lb & 31;
        int tok = sent[b * kL + l];
        float4 v = ((const float4*)(embed + (size_t)tok * kEMB))[tt];
        ushort4 hp;
        unsigned short* hpp = (unsigned short*)&hp;
        float xs[4] = {v.x, v.y, v.z, v.w};
#pragma unroll
        for (int i = 0; i < 4; i++) {
            __nv_bfloat16 h = __float2bfloat16_rn(xs[i]);
            hpp[i] = *(unsigned short*)&h;
        }
        *(ushort4*)(g_xh + (size_t)lb * kEMB + tt * 4) = hp;
    } else {
        int row = blockIdx.x - 4096;      // 0..1023
        int k = threadIdx.x;              // 0..255
        float v = (row < kG) ? Wf[(size_t)row * kEMB + k]
                             : Wb[(size_t)(row - kG) * kEMB + k];
        g_wh[(size_t)row * kEMB + k] = __float2bfloat16_rn(v);
    }
}

// ---------------- K2: mma.sync bf16 GEMM  g_gates = x @ W^T + bias ----------------
// K = 256 (pure bf16 operands).
constexpr int GKC = 64;                 // K per chunk (bf16)
constexpr int NCHUNK = 4;               // 256 / 64
constexpr int GBUF = 32768;             // A(16KB)+B(16KB) per buffer
constexpr int GEMM_SMEM = 2 * GBUF;     // 64 KB

__device__ __forceinline__ void ld_chunk(uint32_t sbase, int ck, int buf, int m0, int n0) {
    const int tid = threadIdx.x;
    const int koff = ck * GKC;
    const uint32_t abase = sbase + buf * GBUF;
    const uint32_t bbase = abase + 16384;
#pragma unroll
    for (int i = 0; i < 4; i++) {
        int idx = i * 256 + tid;        // 0..1023 : 128 rows x 8 16B-chunks
        int r = idx >> 3;
        int c8 = idx & 7;               // 16B chunk within 128B row
        uint32_t so = swz128((uint32_t)(r * 128 + c8 * 16));
        cpasync16(abase + so, g_xh + (size_t)(m0 + r) * kEMB + koff + c8 * 8);
        cpasync16(bbase + so, g_wh + (size_t)(n0 + r) * kEMB + koff + c8 * 8);
    }
}

__global__ __launch_bounds__(256, 2) void k_gemm_mma(const float* __restrict__ biasf,
                                                     const float* __restrict__ biasb) {
    extern __shared__ __align__(1024) char smem[];
    const uint32_t sbase = smem_u32(smem);
    const int tid = threadIdx.x;
    const int wid = tid >> 5;
    const int lane = tid & 31;
    const int m0 = blockIdx.y * 128;
    const int n0 = blockIdx.x * 128;
    const int wm = (wid & 1) * 64;      // warp M offset in tile
    const int wn = (wid >> 1) * 32;     // warp N offset in tile

    float acc[4][4][4];
#pragma unroll
    for (int a = 0; a < 4; a++)
#pragma unroll
        for (int b = 0; b < 4; b++)
#pragma unroll
            for (int c = 0; c < 4; c++) acc[a][b][c] = 0.0f;

    ld_chunk(sbase, 0, 0, m0, n0);
    asm volatile("cp.async.commit_group;");

    const int rbase = (lane & 7) + ((lane >> 3) & 1) * 8;
    const int cext = (lane >> 4) * 16;

    for (int ck = 0; ck < NCHUNK; ck++) {
        if (ck + 1 < NCHUNK) ld_chunk(sbase, ck + 1, (ck + 1) & 1, m0, n0);
        asm volatile("cp.async.commit_group;");
        asm volatile("cp.async.wait_group 1;");
        __syncthreads();

        const uint32_t abuf = sbase + (ck & 1) * GBUF;
        const uint32_t bbuf = abuf + 16384;
#pragma unroll
        for (int k16 = 0; k16 < 4; k16++) {
            const int cb = k16 * 32 + cext;
            uint32_t a[4][4];
#pragma unroll
            for (int mi = 0; mi < 4; mi++)
                ldsm4(a[mi], abuf + swz128((uint32_t)((wm + mi * 16 + rbase) * 128 + cb)));
            uint32_t bfr[2][4];
#pragma unroll
            for (int p = 0; p < 2; p++)
                ldsm4(bfr[p], bbuf + swz128((uint32_t)((wn + p * 16 + rbase) * 128 + cb)));
#pragma unroll
            for (int mi = 0; mi < 4; mi++)
#pragma unroll
                for (int nj = 0; nj < 4; nj++)
                    mma16816(acc[mi][nj], a[mi], bfr[nj >> 1][nj & 1], bfr[nj >> 1][(nj & 1) + 2]);
        }
        __syncthreads();
    }

    // epilogue + bias
#pragma unroll
    for (int mi = 0; mi < 4; mi++) {
        int row = m0 + wm + mi * 16 + (lane >> 2);
#pragma unroll
        for (int nj = 0; nj < 4; nj++) {
            int col = n0 + wn + nj * 8 + (lane & 3) * 2;
            float bx = (col < kG) ? biasf[col] : biasb[col - kG];
            float by = (col + 1 < kG) ? biasf[col + 1] : biasb[col + 1 - kG];
            float2 v0 = make_float2(acc[mi][nj][0] + bx, acc[mi][nj][1] + by);
            float2 v1 = make_float2(acc[mi][nj][2] + bx, acc[mi][nj][3] + by);
            *(float2*)(g_gates + (size_t)row * kN + col) = v0;
            *(float2*)(g_gates + (size_t)(row + 8) * kN + col) = v1;
        }
    }
}

// ---------------- K3: LSTM recurrence (256 thr, 2 gate rows/thread) ----------------
// Row map: thread t owns rows t and t+256. So thread t<128 holds gates
// i (row t) and gg (row 256+t) of unit t IN REGISTERS; thread 128+u holds
// gates f (row 128+u) and o (row 384+u) of unit u. Epilogue (thread t<128)
// reads only f,o through smem (fo_s) — i,gg never round-trip smem.
__global__ __launch_bounds__(256, 1) void k_lstm(const float* __restrict__ Whh_f,
                                                 const float* __restrict__ Whh_b,
                                                 const float* __restrict__ h0,
                                                 const float* __restrict__ c0) {
    __shared__ float fo_s[256];                       // [0..127]=f, [128..255]=o
    __shared__ __align__(16) uint32_t h_bf[64];

    const int t   = threadIdx.x;        // 0..255
    const int blk = blockIdx.x;
    const int dir = blk >> 5;
    const int b   = blk & 31;
    const float* Whh = dir ? Whh_b : Whh_f;
    const int r0 = t;
    const int r1 = t + 256;

    uint32_t w0[64], w1[64];
#pragma unroll
    for (int i = 0; i < 64; i++) {
        float2 a = *(const float2*)(Whh + (size_t)r0 * kH + 2 * i);
        float2 d = *(const float2*)(Whh + (size_t)r1 * kH + 2 * i);
        w0[i] = bfpack(a.y, a.x);
        w1[i] = bfpack(d.y, d.x);
    }

    float c = 0.0f;
    if (t < kH) {
        c = c0[(dir * kB + b) * kH + t];
        float hini = h0[(dir * kB + b) * kH + t];
        float hn = __shfl_down_sync(0xffffffffu, hini, 1);
        if (!(t & 1)) h_bf[t >> 1] = bfpack(hn, hini);
    }
    __syncthreads();

    int l = dir ? (kL - 1) : 0;
    const int step = dir ? -1 : 1;
    const int gofs = dir ? kG : 0;

    float pre0 = g_gates[((size_t)l * kB + b) * kN + gofs + r0];
    float pre1 = g_gates[((size_t)l * kB + b) * kN + gofs + r1];

    for (int s = 0; s < kL; s++) {
        int ln = l + step;
        int lnc = min(max(ln, 0), kL - 1);
        const float* gnext = g_gates + ((size_t)lnc * kB + b) * kN + gofs;
        float pn0 = gnext[r0];
        float pn1 = gnext[r1];

        uint32_t a0 = 0u, a1 = 0u, a2 = 0u, a3 = 0u;
        uint32_t d0 = 0u, d1 = 0u, d2 = 0u, d3 = 0u;
        const uint4* hb = (const uint4*)h_bf;
#pragma unroll
        for (int i = 0; i < 16; i++) {
            uint4 hv = hb[i];
            a0 = hfma2bf(w0[4 * i + 0], hv.x, a0);
            a1 = hfma2bf(w0[4 * i + 1], hv.y, a1);
            a2 = hfma2bf(w0[4 * i + 2], hv.z, a2);
            a3 = hfma2bf(w0[4 * i + 3], hv.w, a3);
            d0 = hfma2bf(w1[4 * i + 0], hv.x, d0);
            d1 = hfma2bf(w1[4 * i + 1], hv.y, d1);
            d2 = hfma2bf(w1[4 * i + 2], hv.z, d2);
            d3 = hfma2bf(w1[4 * i + 3], hv.w, d3);
        }
        float v0 = pre0 + ((bflo(a0) + bfhi(a0)) + (bflo(a1) + bfhi(a1)))
                        + ((bflo(a2) + bfhi(a2)) + (bflo(a3) + bfhi(a3)));
        float v1 = pre1 + ((bflo(d0) + bfhi(d0)) + (bflo(d1) + bfhi(d1)))
                        + ((bflo(d2) + bfhi(d2)) + (bflo(d3) + bfhi(d3)));
        if (t >= kH) {                  // thread 128+u: v0 = gate f(u), v1 = gate o(u)
            fo_s[t - kH] = v0;
            fo_s[t] = v1;               // t = 128+u -> slot 128+u
        }
        __syncthreads();

        if (t < kH) {                   // thread t: v0 = gate i(t), v1 = gate gg(t)
            float gf = fo_s[t];
            float go = fo_s[kH + t];
            c = sigapx(gf) * c + sigapx(v0) * tanhapx(v1);
            float h = sigapx(go) * tanhapx(c);
            float hn = __shfl_down_sync(0xffffffffu, h, 1);
            if (!(t & 1)) h_bf[t >> 1] = bfpack(hn, h);
            g_h[(((size_t)dir * kL + l) * kB + b) * kH + t] = h;
        }
        __syncthreads();

        pre0 = pn0;
        pre1 = pn1;
        l = ln;
    }
}

// ---------------- K4: feats = concat(hf,hb) @ W_tag^T + b_tag ----------------
__global__ void k_feats(const float* __restrict__ Wt, const float* __restrict__ bt) {
    int lb = blockIdx.x * 8 + (threadIdx.x >> 5);
    int lane = threadIdx.x & 31;
    const float4* hbase = (const float4*)g_h;
    float4 a = hbase[(size_t)lb * 32 + lane];
    float4 cc = hbase[(size_t)kL * kB * 32 + (size_t)lb * 32 + lane];
#pragma unroll
    for (int tag = 0; tag < kT; tag++) {
        float4 w0 = *(const float4*)(Wt + tag * 2 * kH + lane * 4);
        float4 w1 = *(const float4*)(Wt + tag * 2 * kH + kH + lane * 4);
        float p = a.x * w0.x + a.y * w0.y + a.z * w0.z + a.w * w0.w
                + cc.x * w1.x + cc.y * w1.y + cc.z * w1.z + cc.w * w1.w;
        p += __shfl_xor_sync(0xffffffffu, p, 16);
        p += __shfl_xor_sync(0xffffffffu, p, 8);
        p += __shfl_xor_sync(0xffffffffu, p, 4);
        p += __shfl_xor_sync(0xffffffffu, p, 2);
        p += __shfl_xor_sync(0xffffffffu, p, 1);
        if (lane == 0) g_feats[(size_t)lb * kT + tag] = p + bt[tag];
    }
}

// ---------------- K5a: CRF chunk matrices ----------------
// Warp-uniform loop bounds (same b,k across warp) -> full-mask shfl OK.
__global__ __launch_bounds__(256) void k_crf_chunks(const float* __restrict__ tr) {
    int gw = blockIdx.x * 8 + (threadIdx.x >> 5);
    int lane = threadIdx.x & 31;
    int b = gw >> 6;
    int k = gw & (kNCH - 1);
    int i = lane / 5; if (i > 4) i = 4;
    int j = lane - (lane / 5) * 5; if (j > 4) j = 4;
    int l0 = 1 + 8 * k;
    int lend = min(l0 + 7, kL - 2);

    float tri[5];
#pragma unroll
    for (int jj = 0; jj < 5; jj++) tri[jj] = tr[i * kT + jj];

    float M = g_feats[((size_t)l0 * kB + b) * kT + i] + tri[j];
    for (int l = l0 + 1; l <= lend; l++) {
        float fi = g_feats[((size_t)l * kB + b) * kT + i];
        float m0 = __shfl_sync(0xffffffffu, M, 0 + j);
        float m1 = __shfl_sync(0xffffffffu, M, 5 + j);
        float m2 = __shfl_sync(0xffffffffu, M, 10 + j);
        float m3 = __shfl_sync(0xffffffffu, M, 15 + j);
        float m4 = __shfl_sync(0xffffffffu, M, 20 + j);
        float t0 = fi + tri[0] + m0, t1 = fi + tri[1] + m1, t2 = fi + tri[2] + m2;
        float t3 = fi + tri[3] + m3, t4 = fi + tri[4] + m4;
        float mx = fmaxf(fmaxf(fmaxf(t0, t1), fmaxf(t2, t3)), t4);
        float ss = __expf(t0 - mx) + __expf(t1 - mx) + __expf(t2 - mx)
                 + __expf(t3 - mx) + __expf(t4 - mx);
        M = mx + __logf(ss);
    }
    if (lane < 25) g_crfM[((size_t)(b * kNCH + k)) * 32 + lane] = M;
}

// ---------------- K5b: CRF apply + gold score ----------------
// Per-subgroup loop trip counts differ within a warp -> subgroup-mask shfl.
__global__ __launch_bounds__(512) void k_crf(const int* __restrict__ tags,
                                             const int* __restrict__ mask,
                                             const float* __restrict__ tr,
                                             float* __restrict__ out) {
    __shared__ float fwd_s[kB];
    __shared__ float gold_s[kB];
    const int tid = threadIdx.x;
    const int w = tid >> 5, lane = tid & 31;

    if (w < 8) {
        const int bi = lane >> 3;
        const int i  = lane & 7;
        const int b  = w * 4 + bi;
        const int ie = (i < kT) ? i : (kT - 1);
        const int base = lane & 24;
        const uint32_t gmask = 0xFFu << base;   // subgroup mask

        float tr0 = tr[ie * kT + 0], tr1 = tr[ie * kT + 1], tr2 = tr[ie * kT + 2];
        float tr3 = tr[ie * kT + 3], tr4 = tr[ie * kT + 4];
        float alpha = (i == START) ? 0.0f : -10000.0f;
        const int mb = mask[b];
        const int K = mb >> 3;          // full chunks

        const float* Cb = g_crfM + (size_t)b * kNCH * 32;
        float cc[5] = {0.f, 0.f, 0.f, 0.f, 0.f};
        if (K > 0) {
#pragma unroll
            for (int jj = 0; jj < 5; jj++) cc[jj] = Cb[ie * 5 + jj];
        }
        for (int k = 0; k < K; k++) {
            float cn[5] = {0.f, 0.f, 0.f, 0.f, 0.f};
            if (k + 1 < K) {
#pragma unroll
                for (int jj = 0; jj < 5; jj++) cn[jj] = Cb[(k + 1) * 32 + ie * 5 + jj];
            }
            float a0 = __shfl_sync(gmask, alpha, base + 0);
            float a1 = __shfl_sync(gmask, alpha, base + 1);
            float a2 = __shfl_sync(gmask, alpha, base + 2);
            float a3 = __shfl_sync(gmask, alpha, base + 3);
            float a4 = __shfl_sync(gmask, alpha, base + 4);
            float t0 = cc[0] + a0, t1 = cc[1] + a1, t2 = cc[2] + a2;
            float t3 = cc[3] + a3, t4 = cc[4] + a4;
            float m = fmaxf(fmaxf(fmaxf(t0, t1), fmaxf(t2, t3)), t4);
            float ss = __expf(t0 - m) + __expf(t1 - m) + __expf(t2 - m)
                     + __expf(t3 - m) + __expf(t4 - m);
            alpha = m + __logf(ss);
#pragma unroll
            for (int jj = 0; jj < 5; jj++) cc[jj] = cn[jj];
        }
        for (int l = 8 * K + 1; l <= mb; l++) {
            float f = g_feats[((size_t)l * kB + b) * kT + ie];
            float a0 = __shfl_sync(gmask, alpha, base + 0);
            float a1 = __shfl_sync(gmask, alpha, base + 1);
            float a2 = __shfl_sync(gmask, alpha, base + 2);
            float a3 = __shfl_sync(gmask, alpha, base + 3);
            float a4 = __shfl_sync(gmask, alpha, base + 4);
            float v0 = a0 + tr0, v1 = a1 + tr1, v2 = a2 + tr2;
            float v3 = a3 + tr3, v4 = a4 + tr4;
            float m = fmaxf(fmaxf(fmaxf(v0, v1), fmaxf(v2, v3)), v4);
            float ss = __expf(v0 - m) + __expf(v1 - m) + __expf(v2 - m)
                     + __expf(v3 - m) + __expf(v4 - m);
            alpha = f + m + __logf(ss);
        }
        float t0 = __shfl_sync(gmask, alpha, base + 0) + tr[STOP * kT + 0];
        float t1 = __shfl_sync(gmask, alpha, base + 1) + tr[STOP * kT + 1];
        float t2 = __shfl_sync(gmask, alpha, base + 2) + tr[STOP * kT + 2];
        float t3 = __shfl_sync(gmask, alpha, base + 3) + tr[STOP * kT + 3];
        float t4 = __shfl_sync(gmask, alpha, base + 4) + tr[STOP * kT + 4];
        float m = fmaxf(fmaxf(fmaxf(t0, t1), fmaxf(t2, t3)), t4);
        float ss = __expf(t0 - m) + __expf(t1 - m) + __expf(t2 - m)
                 + __expf(t3 - m) + __expf(t4 - m);
        if (i == 0) fwd_s[b] = m + __logf(ss);
    } else if (w < 16) {
        const int b = (w - 8) * 4 + (lane >> 3);
        const int lp = lane & 7;
        const int base = lane & 24;
        const uint32_t gmask = 0xFFu << base;
        const int mb = mask[b];
        float s = 0.0f;
        for (int p = lp; p < mb; p += 8) {
            int tp = tags[b * kL + p];
            int tn = tags[b * kL + p + 1];
            s += tr[tn * kT + tp] + g_feats[((size_t)(p + 1) * kB + b) * kT + tn];
        }
        s += __shfl_xor_sync(gmask, s, 4);
        s += __shfl_xor_sync(gmask, s, 2);
        s += __shfl_xor_sync(gmask, s, 1);
        if (lp == 0) gold_s[b] = s + tr[STOP * kT + tags[b * kL + mb]];
    }
    __syncthreads();
    if (tid == 0) {
        float fs = 0.0f, gs = 0.0f;
        for (int bb = 0; bb < kB; bb++) { fs += fwd_s[bb]; gs += gold_s[bb]; }
        out[0] = (fs - gs) * (1.0f / kB);
    }
}

// ---------------- launch ----------------
extern "C" void kernel_launch(void* const* d_in, const int* in_sizes, int n_in,
                              void* d_out, int out_size) {
    const int*   sentence = (const int*)d_in[0];
    const int*   tags     = (const int*)d_in[1];
    const int*   mask     = (const int*)d_in[2];
    const float* embed    = (const float*)d_in[3];
    const float* Wih_f    = (const float*)d_in[4];
    const float* Whh_f    = (const float*)d_in[5];
    const float* b_f      = (const float*)d_in[6];
    const float* Wih_b    = (const float*)d_in[7];
    const float* Whh_b    = (const float*)d_in[8];
    const float* b_b      = (const float*)d_in[9];
    const float* W_tag    = (const float*)d_in[10];
    const float* b_tag    = (const float*)d_in[11];
    const float* trans    = (const float*)d_in[12];
    const float* h0       = (const float*)d_in[13];
    const float* c0       = (const float*)d_in[14];
    (void)in_sizes; (void)n_in; (void)out_size;

    cudaFuncSetAttribute(k_gemm_mma, cudaFuncAttributeMaxDynamicSharedMemorySize, GEMM_SMEM);

    k_prep<<<4096 + 1024, 256>>>(sentence, embed, Wih_f, Wih_b);

    dim3 gg(kN / 128, (kL * kB) / 128);   // (8, 128)
    k_gemm_mma<<<gg, 256, GEMM_SMEM>>>(b_f, b_b);

    k_lstm<<<64, 256>>>(Whh_f, Whh_b, h0, c0);

    k_feats<<<(kL * kB) / 8, 256>>>(W_tag, b_tag);

    k_crf_chunks<<<(kB * kNCH) / 8, 256>>>(trans);

    k_crf<<<1, 512>>>(tags, mask, trans, (float*)d_out);
}